// round 7
// baseline (speedup 1.0000x reference)
#include <cuda_runtime.h>
#include <cuda_bf16.h>
#include <math.h>
#include <stdint.h>

#define BATCH 16
#define TLEN 800
#define DDIM 512
#define VOC 4000
#define VPAD 4096
#define LMAX 100
#define SEXT 201
#define NEMIT 101
#define NROWS (BATCH * TLEN)
#define NTILES 32
#define GSTRIDE 104
#define NEGV (-1e30f)

#define RSTB 80            // smem row stride in bytes (64 int8 + 16 pad)
#define TILE_BYTES 10240   // 128 rows * 80 B
#define STAGE_BYTES 20480  // A tile + B tile
#define NSTAGE 4
#define NKC 8              // 512 / 64
#define DYN_SMEM (NSTAGE * STAGE_BYTES)   // 81920

// ---------------- device scratch ----------------
__device__ __align__(16) char g_Aq[(size_t)NROWS * DDIM];   // int8 A
__device__ __align__(16) char g_Wq[(size_t)VPAD * DDIM];    // int8 W^T [v][k]
__device__ float g_sa[NROWS];
__device__ float g_sw[VPAD];
__device__ unsigned int g_wmaxb[VPAD];
__device__ float g_pmax[NROWS * NTILES];
__device__ float g_psum[NROWS * NTILES];
__device__ float g_gath[(size_t)NROWS * GSTRIDE];
__device__ float g_emit[(size_t)NROWS * NEMIT];
__device__ int   g_slot[BATCH * VOC];
__device__ float g_loss[BATCH];

// ---------------- PTX helpers (compute_103-legal) ----------------------
__device__ __forceinline__ void ldsm4(uint32_t* r, uint32_t addr) {
    asm volatile("ldmatrix.sync.aligned.m8n8.x4.shared.b16 {%0,%1,%2,%3}, [%4];"
                 : "=r"(r[0]), "=r"(r[1]), "=r"(r[2]), "=r"(r[3]) : "r"(addr));
}
__device__ __forceinline__ void mma16832(int* d, const uint32_t* a,
                                         uint32_t b0, uint32_t b1) {
    asm volatile(
        "mma.sync.aligned.m16n8k32.row.col.s32.s8.s8.s32 "
        "{%0,%1,%2,%3}, {%4,%5,%6,%7}, {%8,%9}, {%0,%1,%2,%3};"
        : "+r"(d[0]), "+r"(d[1]), "+r"(d[2]), "+r"(d[3])
        : "r"(a[0]), "r"(a[1]), "r"(a[2]), "r"(a[3]), "r"(b0), "r"(b1));
}
#define CP16(dst, src) \
    asm volatile("cp.async.cg.shared.global [%0], [%1], 16;" :: "r"(dst), "l"(src))
#define CPCOMMIT() asm volatile("cp.async.commit_group;")
#define CPWAIT2()  asm volatile("cp.async.wait_group 2;")

// ---------------- kernel 0a: init slots + wmax -------------------------
__global__ void init_kernel() {
    int i = blockIdx.x * blockDim.x + threadIdx.x;
    if (i < BATCH * VOC) g_slot[i] = -1;
    if (i < VPAD) g_wmaxb[i] = 0u;
}
__global__ void write_slot_kernel(const int* __restrict__ ys_pad) {
    int b = blockIdx.x;
    int j = threadIdx.x;
    if (j < LMAX) g_slot[b * VOC + ys_pad[b * LMAX + j]] = j + 1;
    if (j == LMAX) g_slot[b * VOC + 0] = 0;
}

// ---------------- kernel 0c: quantize A rows (sym, per-row) ------------
__global__ __launch_bounds__(256) void quantA_kernel(const float* __restrict__ src) {
    int row = blockIdx.x * 8 + (threadIdx.x >> 5);
    int lane = threadIdx.x & 31;
    const float* p = src + (size_t)row * DDIM + lane * 16;
    float4 v[4];
#pragma unroll
    for (int i = 0; i < 4; i++) v[i] = *(const float4*)(p + i * 4);
    float amax = 0.f;
#pragma unroll
    for (int i = 0; i < 4; i++) {
        amax = fmaxf(amax, fmaxf(fmaxf(fabsf(v[i].x), fabsf(v[i].y)),
                                 fmaxf(fabsf(v[i].z), fabsf(v[i].w))));
    }
#pragma unroll
    for (int o = 16; o; o >>= 1) amax = fmaxf(amax, __shfl_xor_sync(~0u, amax, o));
    float inv = 127.f / amax;
    uint32_t w[4];
#pragma unroll
    for (int i = 0; i < 4; i++) {
        int q0 = __float2int_rn(v[i].x * inv), q1 = __float2int_rn(v[i].y * inv);
        int q2 = __float2int_rn(v[i].z * inv), q3 = __float2int_rn(v[i].w * inv);
        w[i] = (q0 & 255) | ((q1 & 255) << 8) | ((q2 & 255) << 16) | ((q3 & 255) << 24);
    }
    *(int4*)(g_Aq + (size_t)row * DDIM + lane * 16) =
        make_int4((int)w[0], (int)w[1], (int)w[2], (int)w[3]);
    if (lane == 0) g_sa[row] = amax / 127.f;
}

// ---------------- kernel 0d: W column abs-max (atomic) -----------------
__global__ __launch_bounds__(256) void colmaxW_kernel(const float* __restrict__ W) {
    int v = blockIdx.x * 256 + threadIdx.x;
    if (v >= VOC) return;
    int kbase = blockIdx.y * 64;
    float m = 0.f;
#pragma unroll 8
    for (int kk = 0; kk < 64; kk++)
        m = fmaxf(m, fabsf(W[(size_t)(kbase + kk) * VOC + v]));
    atomicMax(&g_wmaxb[v], __float_as_uint(m));   // non-negative floats: bit-monotonic
}
__global__ void swconv_kernel() {
    int v = blockIdx.x * 256 + threadIdx.x;
    if (v < VPAD) g_sw[v] = (v < VOC) ? __uint_as_float(g_wmaxb[v]) / 127.f : 0.f;
}

// ---------------- kernel 0e: transpose + quantize W -> int8 [v][k] -----
__global__ __launch_bounds__(256) void quantW_kernel(const float* __restrict__ W) {
    __shared__ float sm[32][33];
    int v0 = blockIdx.x * 32, k0 = blockIdx.y * 32;
    int tx = threadIdx.x, ty = threadIdx.y;  // 32 x 8
#pragma unroll
    for (int r = 0; r < 4; r++) {
        int k = k0 + ty + r * 8, v = v0 + tx;
        sm[ty + r * 8][tx] = (v < VOC) ? W[(size_t)k * VOC + v] : 0.f;
    }
    __syncthreads();
#pragma unroll
    for (int r = 0; r < 4; r++) {
        int v = v0 + ty + r * 8, k = k0 + tx;
        float sw = g_sw[v];
        float inv = (sw > 0.f) ? (1.f / sw) : 0.f;
        g_Wq[(size_t)v * DDIM + k] = (char)__float2int_rn(sm[tx][ty + r * 8] * inv);
    }
}

// ---------------- kernel 1: int8 cp.async mma.sync GEMM ----------------
// 128x128 tiles, k-chunk 64 int8, 256 threads (8 warps 2x4), warp 64x32.
__global__ __launch_bounds__(256, 2)
void mma_gemm_kernel(const float* __restrict__ bias) {
    extern __shared__ __align__(128) char dynbuf[];
    __shared__ float bias_s[128];
    __shared__ float sw_s[128];
    __shared__ int   slot_s[256];
    __shared__ float redM[128 * 5];
    __shared__ float redS[128 * 5];

    const uint32_t sbD = (uint32_t)__cvta_generic_to_shared(dynbuf);
    const int tid = threadIdx.x;
    const int lane = tid & 31, wid = tid >> 5;
    const int wm = wid >> 2, wn = wid & 3;
    const int n0 = blockIdx.x * 128, m0 = blockIdx.y * 128;
    const int rb0 = m0 / TLEN, rb1 = (m0 + 127) / TLEN;

    if (tid < 128) {
        int gc = n0 + tid;
        bias_s[tid]       = (gc < VOC) ? bias[gc] : 0.f;
        sw_s[tid]         = (gc < VOC) ? g_sw[gc] : 0.f;
        slot_s[tid]       = (gc < VOC) ? g_slot[rb0 * VOC + gc] : -1;
        slot_s[128 + tid] = (gc < VOC) ? g_slot[rb1 * VOC + gc] : -1;
    }

    // each stage: A 128x64B + B 128x64B; each thread 2 A-chunks + 2 B-chunks
    const int r0i = tid >> 2,         c0i = tid & 3;
    const int r1i = (tid + 256) >> 2, c1i = (tid + 256) & 3;
    const char* Ab = g_Aq + (size_t)m0 * DDIM;
    const char* Bb = g_Wq + (size_t)n0 * DDIM;

#pragma unroll
    for (int s = 0; s < NSTAGE - 1; s++) {
        uint32_t dst = sbD + s * STAGE_BYTES;
        int k0 = s * 64;
        CP16(dst + r0i * RSTB + c0i * 16,              Ab + (size_t)r0i * DDIM + k0 + c0i * 16);
        CP16(dst + r1i * RSTB + c1i * 16,              Ab + (size_t)r1i * DDIM + k0 + c1i * 16);
        CP16(dst + TILE_BYTES + r0i * RSTB + c0i * 16, Bb + (size_t)r0i * DDIM + k0 + c0i * 16);
        CP16(dst + TILE_BYTES + r1i * RSTB + c1i * 16, Bb + (size_t)r1i * DDIM + k0 + c1i * 16);
        CPCOMMIT();
    }

    int acc[4][16];
#pragma unroll
    for (int i = 0; i < 4; i++)
#pragma unroll
        for (int j = 0; j < 16; j++) acc[i][j] = 0;

    const uint32_t aRow = (uint32_t)((wm * 64 + (lane & 15)) * RSTB + (lane >> 4) * 16);
    const uint32_t bRow = (uint32_t)((wn * 32 + (lane & 15)) * RSTB + (lane >> 4) * 16) + TILE_BYTES;

    for (int kc = 0; kc < NKC; kc++) {
        CPWAIT2();
        __syncthreads();

        int ks = kc + NSTAGE - 1;
        if (ks < NKC) {
            uint32_t dst = sbD + (ks & 3) * STAGE_BYTES;
            int k0 = ks * 64;
            CP16(dst + r0i * RSTB + c0i * 16,              Ab + (size_t)r0i * DDIM + k0 + c0i * 16);
            CP16(dst + r1i * RSTB + c1i * 16,              Ab + (size_t)r1i * DDIM + k0 + c1i * 16);
            CP16(dst + TILE_BYTES + r0i * RSTB + c0i * 16, Bb + (size_t)r0i * DDIM + k0 + c0i * 16);
            CP16(dst + TILE_BYTES + r1i * RSTB + c1i * 16, Bb + (size_t)r1i * DDIM + k0 + c1i * 16);
        }
        CPCOMMIT();

        const uint32_t base = sbD + (kc & 3) * STAGE_BYTES;
#pragma unroll
        for (int h = 0; h < 2; h++) {   // two k=32 halves of the 64B rows
            uint32_t af[4][4], bf[2][4];
#pragma unroll
            for (int mf = 0; mf < 4; mf++)
                ldsm4(af[mf], base + aRow + mf * (16 * RSTB) + h * 32);
#pragma unroll
            for (int jg = 0; jg < 2; jg++)
                ldsm4(bf[jg], base + bRow + jg * (16 * RSTB) + h * 32);
#pragma unroll
            for (int mf = 0; mf < 4; mf++) {
#pragma unroll
                for (int jg = 0; jg < 2; jg++) {
                    mma16832(&acc[mf][(jg * 2 + 0) * 4], af[mf], bf[jg][0], bf[jg][2]);
                    mma16832(&acc[mf][(jg * 2 + 1) * 4], af[mf], bf[jg][1], bf[jg][3]);
                }
            }
        }
    }

    // ---- epilogue: dequant + bias + online max/sumexp + label gather ----
    float biasv[8], swv[8]; bool validv[8]; int sl0[8], sl1[8];
#pragma unroll
    for (int nf = 0; nf < 4; nf++)
#pragma unroll
        for (int e = 0; e < 2; e++) {
            int idx = nf * 2 + e;
            int c = wn * 32 + nf * 8 + (lane & 3) * 2 + e;
            biasv[idx]  = bias_s[c];
            swv[idx]    = sw_s[c];
            validv[idx] = (n0 + c) < VOC;
            sl0[idx] = slot_s[c];
            sl1[idx] = slot_s[128 + c];
        }

#pragma unroll
    for (int mf = 0; mf < 4; mf++) {
#pragma unroll
        for (int half = 0; half < 2; half++) {
            int r = wm * 64 + mf * 16 + half * 8 + (lane >> 2);
            int grow = m0 + r;
            int bb = (rb1 > rb0 && grow >= rb1 * TLEN) ? 1 : 0;
            float saf = g_sa[grow];
            float vv[8];
#pragma unroll
            for (int nf = 0; nf < 4; nf++)
#pragma unroll
                for (int e = 0; e < 2; e++) {
                    int ci = nf * 2 + e;
                    vv[ci] = fmaf((float)acc[mf][nf * 4 + half * 2 + e],
                                  saf * swv[ci], biasv[ci]);
                }
            float m = -3.4e38f, s = 0.f;
#pragma unroll
            for (int ci = 0; ci < 8; ci++)
                if (validv[ci]) m = fmaxf(m, vv[ci]);
#pragma unroll
            for (int ci = 0; ci < 8; ci++) {
                if (validv[ci]) {
                    s += __expf(vv[ci] - m);
                    int sl = bb ? sl1[ci] : sl0[ci];
                    if (sl >= 0) g_gath[(size_t)grow * GSTRIDE + sl] = vv[ci];
                }
            }
#pragma unroll
            for (int off = 1; off <= 2; off <<= 1) {
                float om = __shfl_xor_sync(~0u, m, off);
                float os = __shfl_xor_sync(~0u, s, off);
                float nm = fmaxf(m, om);
                s = s * __expf(m - nm) + os * __expf(om - nm);
                m = nm;
            }
            if ((lane & 3) == 0) { redM[r * 5 + wn] = m; redS[r * 5 + wn] = s; }
        }
    }
    __syncthreads();
    if (tid < 128) {
        float M = redM[tid * 5 + 0], S = redS[tid * 5 + 0];
#pragma unroll
        for (int w = 1; w < 4; w++) {
            float m2 = redM[tid * 5 + w], s2 = redS[tid * 5 + w];
            float Mn = fmaxf(M, m2);
            S = S * __expf(M - Mn) + s2 * __expf(m2 - Mn);
            M = Mn;
        }
        g_pmax[(m0 + tid) * NTILES + blockIdx.x] = M;
        g_psum[(m0 + tid) * NTILES + blockIdx.x] = S;
    }
}

// ---------------- kernel 2: fused LSE reduce + emit expand -------------
__global__ __launch_bounds__(128) void emit_kernel(const int* __restrict__ ys_pad) {
    const int row = blockIdx.x;
    const int tid = threadIdx.x;
    __shared__ float lse_s;
    if (tid < 32) {
        float pm = g_pmax[row * NTILES + tid];
        float ps = g_psum[row * NTILES + tid];
        float M = pm;
#pragma unroll
        for (int o = 16; o; o >>= 1) M = fmaxf(M, __shfl_xor_sync(~0u, M, o));
        float v = ps * __expf(pm - M);
#pragma unroll
        for (int o = 16; o; o >>= 1) v += __shfl_xor_sync(~0u, v, o);
        if (tid == 0) lse_s = M + __logf(v);
    }
    __syncthreads();
    if (tid < NEMIT) {
        int b = row / TLEN;
        int col = (tid == 0) ? 0 : ys_pad[b * LMAX + tid - 1];
        int slot = g_slot[b * VOC + col];
        g_emit[(size_t)row * NEMIT + tid] = g_gath[(size_t)row * GSTRIDE + slot] - lse_s;
    }
}

// ---------------- kernel 3: CTC forward recursion ----------------------
__global__ __launch_bounds__(224) void ctc_kernel(const int* __restrict__ hlens,
                                                  const int* __restrict__ ys_pad,
                                                  const int* __restrict__ ys_lens) {
    const int b = blockIdx.x;
    const int s = threadIdx.x;
    __shared__ float al[2][SEXT + 2];

    const float* eb = g_emit + (size_t)b * TLEN * NEMIT;
    const bool act = s < SEXT;
    const int j = (s & 1) ? ((s >> 1) + 1) : 0;

    bool skip = false;
    if (act && (s & 1) && s >= 3) {
        int cur  = ys_pad[b * LMAX + (s >> 1)];
        int prev = ys_pad[b * LMAX + (s >> 1) - 1];
        skip = (cur != prev);
    }

    if (s < 2) { al[0][s] = NEGV; al[1][s] = NEGV; }
    if (act) al[0][s + 2] = (s < 2) ? eb[j] : NEGV;

    const int hl = hlens[b];
    float e1 = NEGV;
    if (act && hl > 1) e1 = eb[NEMIT + j];
    __syncthreads();

    int p = 0;
    for (int t = 1; t < hl; t++) {
        float e = e1;
        if (act && t + 1 < hl) e1 = eb[(size_t)(t + 1) * NEMIT + j];

        if (act) {
            float a0 = al[p][s + 2];
            float a1 = al[p][s + 1];
            float a2 = skip ? al[p][s] : NEGV;
            float m = fmaxf(a0, fmaxf(a1, a2));
            float w = __expf(a0 - m) + __expf(a1 - m) + __expf(a2 - m);
            al[1 - p][s + 2] = m + __logf(w) + e;
        }
        __syncthreads();
        p ^= 1;
    }

    if (s == 0) {
        int L = ys_lens[b];
        int idx = 2 * L;
        float aL = al[p][idx + 2];
        float aP = al[p][idx + 1];
        float m = fmaxf(aL, aP);
        float loss = -(m + __logf(__expf(aL - m) + __expf(aP - m)));
        if (!isfinite(loss) || loss >= 1e29f) loss = 0.f;
        g_loss[b] = loss;
    }
}

// ---------------- kernel 4: final reduce --------------------------------
__global__ void finalize_kernel(float* __restrict__ out) {
    float sum = 0.f;
    for (int i = 0; i < BATCH; i++) sum += g_loss[i];
    out[0] = sum / (float)BATCH;
}

// ---------------- launch --------------------------------------------------
extern "C" void kernel_launch(void* const* d_in, const int* in_sizes, int n_in,
                              void* d_out, int out_size) {
    const float* hs     = (const float*)d_in[0];
    const float* Wm     = (const float*)d_in[1];
    const float* bias   = (const float*)d_in[2];
    const int* hlens    = (const int*)d_in[3];
    const int* ys_pad   = (const int*)d_in[4];
    const int* ys_lens  = (const int*)d_in[5];
    float* out = (float*)d_out;

    cudaFuncSetAttribute(mma_gemm_kernel,
                         cudaFuncAttributeMaxDynamicSharedMemorySize, DYN_SMEM);

    init_kernel<<<(BATCH * VOC + 255) / 256, 256>>>();
    write_slot_kernel<<<BATCH, 128>>>(ys_pad);
    quantA_kernel<<<NROWS / 8, 256>>>(hs);
    colmaxW_kernel<<<dim3((VOC + 255) / 256, DDIM / 64), 256>>>(Wm);
    swconv_kernel<<<VPAD / 256, 256>>>();
    quantW_kernel<<<dim3(VPAD / 32, DDIM / 32), dim3(32, 8)>>>(Wm);

    dim3 gemm_grid(NTILES, NROWS / 128);  // (32, 100)
    mma_gemm_kernel<<<gemm_grid, 256, DYN_SMEM>>>(bias);

    emit_kernel<<<NROWS, 128>>>(ys_pad);
    ctc_kernel<<<BATCH, 224>>>(hlens, ys_pad, ys_lens);
    finalize_kernel<<<1, 1>>>(out);
}

// round 8
// speedup vs baseline: 1.4767x; 1.4767x over previous
#include <cuda_runtime.h>
#include <cuda_bf16.h>
#include <math.h>
#include <stdint.h>

#define BATCH 16
#define TLEN 800
#define DDIM 512
#define VOC 4000
#define VPAD 4096
#define LMAX 100
#define SEXT 201
#define NEMIT 101
#define NROWS (BATCH * TLEN)
#define NTILES 32
#define GSTRIDE 104
#define NEGV (-1e30f)

#define RSTB 80            // smem row stride in bytes (40 bf16)
#define TILE_BYTES 10240   // 128 rows * 80 B
#define STAGE_BYTES 20480  // A tile + B tile
#define NSTAGE 4
#define DYN_SMEM (NSTAGE * STAGE_BYTES)   // 81920

// ---------------- device scratch ----------------
__device__ __align__(16) __nv_bfloat16 g_Abf[(size_t)NROWS * DDIM];
__device__ __align__(16) __nv_bfloat16 g_Wt[(size_t)VPAD * DDIM];
__device__ float g_pmax[NROWS * NTILES];
__device__ float g_psum[NROWS * NTILES];
__device__ float g_gath[(size_t)NROWS * GSTRIDE];
__device__ float g_emit[(size_t)NROWS * NEMIT];
__device__ int   g_slot[BATCH * VOC];
__device__ float g_loss[BATCH];

// ---------------- PTX helpers (compute_103-legal) ----------------------
__device__ __forceinline__ void ldsm4(uint32_t* r, uint32_t addr) {
    asm volatile("ldmatrix.sync.aligned.m8n8.x4.shared.b16 {%0,%1,%2,%3}, [%4];"
                 : "=r"(r[0]), "=r"(r[1]), "=r"(r[2]), "=r"(r[3]) : "r"(addr));
}
__device__ __forceinline__ void mma16816(float* d, const uint32_t* a,
                                         uint32_t b0, uint32_t b1) {
    asm volatile(
        "mma.sync.aligned.m16n8k16.row.col.f32.bf16.bf16.f32 "
        "{%0,%1,%2,%3}, {%4,%5,%6,%7}, {%8,%9}, {%0,%1,%2,%3};"
        : "+f"(d[0]), "+f"(d[1]), "+f"(d[2]), "+f"(d[3])
        : "r"(a[0]), "r"(a[1]), "r"(a[2]), "r"(a[3]), "r"(b0), "r"(b1));
}
#define CP16(dst, src) \
    asm volatile("cp.async.cg.shared.global [%0], [%1], 16;" :: "r"(dst), "l"(src))
#define CPCOMMIT() asm volatile("cp.async.commit_group;")
#define CPWAIT2()  asm volatile("cp.async.wait_group 2;")

// ---------------- kernel 0a/0b: slot map ------------------------------
__global__ void init_slot_kernel() {
    int i = blockIdx.x * blockDim.x + threadIdx.x;
    if (i < BATCH * VOC) g_slot[i] = -1;
}
__global__ void write_slot_kernel(const int* __restrict__ ys_pad) {
    int b = blockIdx.x;
    int j = threadIdx.x;
    if (j < LMAX) g_slot[b * VOC + ys_pad[b * LMAX + j]] = j + 1;
    if (j == LMAX) g_slot[b * VOC + 0] = 0;
}

// ---------------- kernel 0c: convert A to bf16 -------------------------
__global__ __launch_bounds__(256) void convA_kernel(const float* __restrict__ src) {
    size_t i = (size_t)(blockIdx.x * blockDim.x + threadIdx.x) * 4;
    if (i < (size_t)NROWS * DDIM) {
        float4 v = *(const float4*)(src + i);
        *(__nv_bfloat162*)(g_Abf + i)     = __floats2bfloat162_rn(v.x, v.y);
        *(__nv_bfloat162*)(g_Abf + i + 2) = __floats2bfloat162_rn(v.z, v.w);
    }
}

// ---------------- kernel 0d: transpose W -> [VPAD, DDIM] bf16 ----------
__global__ __launch_bounds__(256) void transW_kernel(const float* __restrict__ W) {
    __shared__ float sm[32][33];
    int v0 = blockIdx.x * 32, k0 = blockIdx.y * 32;
    int tx = threadIdx.x, ty = threadIdx.y;  // 32 x 8
#pragma unroll
    for (int r = 0; r < 4; r++) {
        int k = k0 + ty + r * 8, v = v0 + tx;
        sm[ty + r * 8][tx] = (v < VOC) ? W[(size_t)k * VOC + v] : 0.f;
    }
    __syncthreads();
#pragma unroll
    for (int r = 0; r < 4; r++) {
        int v = v0 + ty + r * 8, k = k0 + tx;
        g_Wt[(size_t)v * DDIM + k] = __float2bfloat16(sm[tx][ty + r * 8]);
    }
}

// ---------------- kernel 1: cp.async-pipelined mma.sync GEMM -----------
// 128x128x32 tiles, 256 threads (8 warps, 2x4), warp tile 64x32, 4 stages.
// Skips m-tiles whose rows are all beyond hlen (CTC never reads them).
__global__ __launch_bounds__(256, 2)
void mma_gemm_kernel(const float* __restrict__ bias,
                     const int* __restrict__ hlens) {
    extern __shared__ __align__(128) char dynbuf[];
    __shared__ float bias_s[128];
    __shared__ int   slot_s[256];
    __shared__ float redM[128 * 5];
    __shared__ float redS[128 * 5];

    const int n0 = blockIdx.x * 128, m0 = blockIdx.y * 128;
    const int rb0 = m0 / TLEN, rb1 = (m0 + 127) / TLEN;

    // dead-tile skip: all 128 rows belong to one batch and start at t >= hlen
    if (rb0 == rb1 && (m0 - rb0 * TLEN) >= hlens[rb0]) return;

    const uint32_t sbD = (uint32_t)__cvta_generic_to_shared(dynbuf);
    const int tid = threadIdx.x;
    const int lane = tid & 31, wid = tid >> 5;
    const int wm = wid >> 2, wn = wid & 3;

    if (tid < 128) {
        int gc = n0 + tid;
        bias_s[tid]       = (gc < VOC) ? bias[gc] : 0.f;
        slot_s[tid]       = (gc < VOC) ? g_slot[rb0 * VOC + gc] : -1;
        slot_s[128 + tid] = (gc < VOC) ? g_slot[rb1 * VOC + gc] : -1;
    }

    // gmem->smem chunk mapping: each thread moves 2 chunks of A, 2 of B
    const int r0i = tid >> 2,         c0i = tid & 3;
    const int r1i = (tid + 256) >> 2, c1i = (tid + 256) & 3;
    const __nv_bfloat16* Ab = g_Abf + (size_t)m0 * DDIM;
    const __nv_bfloat16* Bb = g_Wt  + (size_t)n0 * DDIM;

    // prologue: issue stages 0..2
#pragma unroll
    for (int s = 0; s < NSTAGE - 1; s++) {
        uint32_t dst = sbD + s * STAGE_BYTES;
        int k0 = s * 32;
        CP16(dst + r0i * RSTB + c0i * 16,              Ab + (size_t)r0i * DDIM + k0 + c0i * 8);
        CP16(dst + r1i * RSTB + c1i * 16,              Ab + (size_t)r1i * DDIM + k0 + c1i * 8);
        CP16(dst + TILE_BYTES + r0i * RSTB + c0i * 16, Bb + (size_t)r0i * DDIM + k0 + c0i * 8);
        CP16(dst + TILE_BYTES + r1i * RSTB + c1i * 16, Bb + (size_t)r1i * DDIM + k0 + c1i * 8);
        CPCOMMIT();
    }

    float acc[4][16];
#pragma unroll
    for (int i = 0; i < 4; i++)
#pragma unroll
        for (int j = 0; j < 16; j++) acc[i][j] = 0.f;

    const uint32_t aRow = (uint32_t)((wm * 64 + (lane & 15)) * RSTB + (lane >> 4) * 16);
    const uint32_t bRow = (uint32_t)((wn * 32 + (lane & 15)) * RSTB + (lane >> 4) * 16) + TILE_BYTES;

    for (int kc = 0; kc < 16; kc++) {
        CPWAIT2();            // stage kc complete (this thread)
        __syncthreads();      // all threads' stage kc visible; prior reads done

        int ks = kc + NSTAGE - 1;
        if (ks < 16) {
            uint32_t dst = sbD + (ks & 3) * STAGE_BYTES;
            int k0 = ks * 32;
            CP16(dst + r0i * RSTB + c0i * 16,              Ab + (size_t)r0i * DDIM + k0 + c0i * 8);
            CP16(dst + r1i * RSTB + c1i * 16,              Ab + (size_t)r1i * DDIM + k0 + c1i * 8);
            CP16(dst + TILE_BYTES + r0i * RSTB + c0i * 16, Bb + (size_t)r0i * DDIM + k0 + c0i * 8);
            CP16(dst + TILE_BYTES + r1i * RSTB + c1i * 16, Bb + (size_t)r1i * DDIM + k0 + c1i * 8);
        }
        CPCOMMIT();           // always commit to keep wait counts exact

        const uint32_t base = sbD + (kc & 3) * STAGE_BYTES;
#pragma unroll
        for (int h = 0; h < 2; h++) {
            uint32_t af[4][4], bf[2][4];
#pragma unroll
            for (int mf = 0; mf < 4; mf++)
                ldsm4(af[mf], base + aRow + mf * (16 * RSTB) + h * 32);
#pragma unroll
            for (int jg = 0; jg < 2; jg++)
                ldsm4(bf[jg], base + bRow + jg * (16 * RSTB) + h * 32);
#pragma unroll
            for (int mf = 0; mf < 4; mf++) {
#pragma unroll
                for (int jg = 0; jg < 2; jg++) {
                    mma16816(&acc[mf][(jg * 2 + 0) * 4], af[mf], bf[jg][0], bf[jg][2]);
                    mma16816(&acc[mf][(jg * 2 + 1) * 4], af[mf], bf[jg][1], bf[jg][3]);
                }
            }
        }
    }

    // ---- epilogue: bias + online max/sumexp + label gather ----
    float biasv[8]; bool validv[8]; int sl0[8], sl1[8];
#pragma unroll
    for (int nf = 0; nf < 4; nf++)
#pragma unroll
        for (int e = 0; e < 2; e++) {
            int idx = nf * 2 + e;
            int c = wn * 32 + nf * 8 + (lane & 3) * 2 + e;
            biasv[idx]  = bias_s[c];
            validv[idx] = (n0 + c) < VOC;
            sl0[idx] = slot_s[c];
            sl1[idx] = slot_s[128 + c];
        }
#pragma unroll
    for (int mf = 0; mf < 4; mf++)
#pragma unroll
        for (int k = 0; k < 16; k++)
            acc[mf][k] += biasv[(k >> 2) * 2 + (k & 1)];

#pragma unroll
    for (int mf = 0; mf < 4; mf++) {
#pragma unroll
        for (int half = 0; half < 2; half++) {
            int r = wm * 64 + mf * 16 + half * 8 + (lane >> 2);
            int grow = m0 + r;
            int bb = (rb1 > rb0 && grow >= rb1 * TLEN) ? 1 : 0;
            float m = -3.4e38f, s = 0.f;
#pragma unroll
            for (int nf = 0; nf < 4; nf++)
#pragma unroll
                for (int e = 0; e < 2; e++) {
                    float v = acc[mf][nf * 4 + half * 2 + e];
                    if (validv[nf * 2 + e]) m = fmaxf(m, v);
                }
#pragma unroll
            for (int nf = 0; nf < 4; nf++)
#pragma unroll
                for (int e = 0; e < 2; e++) {
                    int ci = nf * 2 + e;
                    float v = acc[mf][nf * 4 + half * 2 + e];
                    if (validv[ci]) {
                        s += __expf(v - m);
                        int sl = bb ? sl1[ci] : sl0[ci];
                        if (sl >= 0) g_gath[(size_t)grow * GSTRIDE + sl] = v;
                    }
                }
#pragma unroll
            for (int off = 1; off <= 2; off <<= 1) {
                float om = __shfl_xor_sync(~0u, m, off);
                float os = __shfl_xor_sync(~0u, s, off);
                float nm = fmaxf(m, om);
                s = s * __expf(m - nm) + os * __expf(om - nm);
                m = nm;
            }
            if ((lane & 3) == 0) { redM[r * 5 + wn] = m; redS[r * 5 + wn] = s; }
        }
    }
    __syncthreads();
    if (tid < 128) {
        float M = redM[tid * 5 + 0], S = redS[tid * 5 + 0];
#pragma unroll
        for (int w = 1; w < 4; w++) {
            float m2 = redM[tid * 5 + w], s2 = redS[tid * 5 + w];
            float Mn = fmaxf(M, m2);
            S = S * __expf(M - Mn) + s2 * __expf(m2 - Mn);
            M = Mn;
        }
        g_pmax[(m0 + tid) * NTILES + blockIdx.x] = M;
        g_psum[(m0 + tid) * NTILES + blockIdx.x] = S;
    }
}

// ---------------- kernel 2: fused LSE reduce + emit expand -------------
// Rows with t >= hlen are skipped by the CTC; their garbage values are harmless,
// but skip the work anyway.
__global__ __launch_bounds__(128) void emit_kernel(const int* __restrict__ ys_pad,
                                                   const int* __restrict__ hlens) {
    const int row = blockIdx.x;
    const int b = row / TLEN;
    if ((row - b * TLEN) >= hlens[b]) return;
    const int tid = threadIdx.x;
    __shared__ float lse_s;
    if (tid < 32) {
        float pm = g_pmax[row * NTILES + tid];
        float ps = g_psum[row * NTILES + tid];
        float M = pm;
#pragma unroll
        for (int o = 16; o; o >>= 1) M = fmaxf(M, __shfl_xor_sync(~0u, M, o));
        float v = ps * __expf(pm - M);
#pragma unroll
        for (int o = 16; o; o >>= 1) v += __shfl_xor_sync(~0u, v, o);
        if (tid == 0) lse_s = M + __logf(v);
    }
    __syncthreads();
    if (tid < NEMIT) {
        int col = (tid == 0) ? 0 : ys_pad[b * LMAX + tid - 1];
        int slot = g_slot[b * VOC + col];
        g_emit[(size_t)row * NEMIT + tid] = g_gath[(size_t)row * GSTRIDE + slot] - lse_s;
    }
}

// ---------------- kernel 3: CTC forward recursion ----------------------
__global__ __launch_bounds__(224) void ctc_kernel(const int* __restrict__ hlens,
                                                  const int* __restrict__ ys_pad,
                                                  const int* __restrict__ ys_lens) {
    const int b = blockIdx.x;
    const int s = threadIdx.x;
    __shared__ float al[2][SEXT + 2];

    const float* eb = g_emit + (size_t)b * TLEN * NEMIT;
    const bool act = s < SEXT;
    const int j = (s & 1) ? ((s >> 1) + 1) : 0;

    bool skip = false;
    if (act && (s & 1) && s >= 3) {
        int cur  = ys_pad[b * LMAX + (s >> 1)];
        int prev = ys_pad[b * LMAX + (s >> 1) - 1];
        skip = (cur != prev);
    }

    if (s < 2) { al[0][s] = NEGV; al[1][s] = NEGV; }
    if (act) al[0][s + 2] = (s < 2) ? eb[j] : NEGV;

    const int hl = hlens[b];
    float e1 = NEGV;
    if (act && hl > 1) e1 = eb[NEMIT + j];
    __syncthreads();

    int p = 0;
    for (int t = 1; t < hl; t++) {
        float e = e1;
        if (act && t + 1 < hl) e1 = eb[(size_t)(t + 1) * NEMIT + j];

        if (act) {
            float a0 = al[p][s + 2];
            float a1 = al[p][s + 1];
            float a2 = skip ? al[p][s] : NEGV;
            float m = fmaxf(a0, fmaxf(a1, a2));
            float w = __expf(a0 - m) + __expf(a1 - m) + __expf(a2 - m);
            al[1 - p][s + 2] = m + __logf(w) + e;
        }
        __syncthreads();
        p ^= 1;
    }

    if (s == 0) {
        int L = ys_lens[b];
        int idx = 2 * L;
        float aL = al[p][idx + 2];
        float aP = al[p][idx + 1];
        float m = fmaxf(aL, aP);
        float loss = -(m + __logf(__expf(aL - m) + __expf(aP - m)));
        if (!isfinite(loss) || loss >= 1e29f) loss = 0.f;
        g_loss[b] = loss;
    }
}

// ---------------- kernel 4: final reduce --------------------------------
__global__ void finalize_kernel(float* __restrict__ out) {
    float sum = 0.f;
    for (int i = 0; i < BATCH; i++) sum += g_loss[i];
    out[0] = sum / (float)BATCH;
}

// ---------------- launch --------------------------------------------------
extern "C" void kernel_launch(void* const* d_in, const int* in_sizes, int n_in,
                              void* d_out, int out_size) {
    const float* hs     = (const float*)d_in[0];
    const float* Wm     = (const float*)d_in[1];
    const float* bias   = (const float*)d_in[2];
    const int* hlens    = (const int*)d_in[3];
    const int* ys_pad   = (const int*)d_in[4];
    const int* ys_lens  = (const int*)d_in[5];
    float* out = (float*)d_out;

    cudaFuncSetAttribute(mma_gemm_kernel,
                         cudaFuncAttributeMaxDynamicSharedMemorySize, DYN_SMEM);

    init_slot_kernel<<<(BATCH * VOC + 255) / 256, 256>>>();
    write_slot_kernel<<<BATCH, 128>>>(ys_pad);
    convA_kernel<<<(NROWS * DDIM / 4 + 255) / 256, 256>>>(hs);
    transW_kernel<<<dim3(VPAD / 32, DDIM / 32), dim3(32, 8)>>>(Wm);

    dim3 gemm_grid(NTILES, NROWS / 128);  // (32, 100)
    mma_gemm_kernel<<<gemm_grid, 256, DYN_SMEM>>>(bias, hlens);

    emit_kernel<<<NROWS, 128>>>(ys_pad, hlens);
    ctc_kernel<<<BATCH, 224>>>(hlens, ys_pad, ys_lens);
    finalize_kernel<<<1, 1>>>(out);
}

// round 9
// speedup vs baseline: 1.6187x; 1.0961x over previous
#include <cuda_runtime.h>
#include <cuda_bf16.h>
#include <math.h>
#include <stdint.h>

#define BATCH 16
#define TLEN 800
#define DDIM 512
#define VOC 4000
#define VPAD 4096
#define LMAX 100
#define SEXT 201
#define NEMIT 101
#define NROWS (BATCH * TLEN)
#define NTILES 32
#define GSTRIDE 104
#define NEGV (-1e30f)

#define KCHUNK 64
#define NKC 8                 // 512 / 64
#define TILE_BYTES 16384      // 128 rows * 128 B (XOR swizzle, no pad)
#define STAGE_BYTES 32768     // A tile + B tile
#define NSTAGE 3
#define DYN_SMEM (NSTAGE * STAGE_BYTES)   // 98304

// ---------------- device scratch ----------------
__device__ __align__(16) __nv_bfloat16 g_Abf[(size_t)NROWS * DDIM];
__device__ __align__(16) __nv_bfloat16 g_Wt[(size_t)VPAD * DDIM];
__device__ float g_pmax[NROWS * NTILES];
__device__ float g_psum[NROWS * NTILES];
__device__ float g_gath[(size_t)NROWS * GSTRIDE];
__device__ float g_emit[(size_t)NROWS * NEMIT];
__device__ int   g_slot[BATCH * VOC];
__device__ float g_loss[BATCH];

// ---------------- PTX helpers (compute_103-legal) ----------------------
__device__ __forceinline__ void ldsm4(uint32_t* r, uint32_t addr) {
    asm volatile("ldmatrix.sync.aligned.m8n8.x4.shared.b16 {%0,%1,%2,%3}, [%4];"
                 : "=r"(r[0]), "=r"(r[1]), "=r"(r[2]), "=r"(r[3]) : "r"(addr));
}
__device__ __forceinline__ void mma16816(float* d, const uint32_t* a,
                                         uint32_t b0, uint32_t b1) {
    asm volatile(
        "mma.sync.aligned.m16n8k16.row.col.f32.bf16.bf16.f32 "
        "{%0,%1,%2,%3}, {%4,%5,%6,%7}, {%8,%9}, {%0,%1,%2,%3};"
        : "+f"(d[0]), "+f"(d[1]), "+f"(d[2]), "+f"(d[3])
        : "r"(a[0]), "r"(a[1]), "r"(a[2]), "r"(a[3]), "r"(b0), "r"(b1));
}
#define CP16(dst, src) \
    asm volatile("cp.async.cg.shared.global [%0], [%1], 16;" :: "r"(dst), "l"(src))
#define CPCOMMIT() asm volatile("cp.async.commit_group;")
#define CPWAIT1()  asm volatile("cp.async.wait_group 1;")

// ---------------- kernel 0a/0b: slot map ------------------------------
__global__ void init_slot_kernel() {
    int i = blockIdx.x * blockDim.x + threadIdx.x;
    if (i < BATCH * VOC) g_slot[i] = -1;
}
__global__ void write_slot_kernel(const int* __restrict__ ys_pad) {
    int b = blockIdx.x;
    int j = threadIdx.x;
    if (j < LMAX) g_slot[b * VOC + ys_pad[b * LMAX + j]] = j + 1;
    if (j == LMAX) g_slot[b * VOC + 0] = 0;
}

// ---------------- kernel 0c: convert A to bf16 -------------------------
__global__ __launch_bounds__(256) void convA_kernel(const float* __restrict__ src) {
    size_t i = (size_t)(blockIdx.x * blockDim.x + threadIdx.x) * 4;
    if (i < (size_t)NROWS * DDIM) {
        float4 v = *(const float4*)(src + i);
        *(__nv_bfloat162*)(g_Abf + i)     = __floats2bfloat162_rn(v.x, v.y);
        *(__nv_bfloat162*)(g_Abf + i + 2) = __floats2bfloat162_rn(v.z, v.w);
    }
}

// ---------------- kernel 0d: transpose W -> [VPAD, DDIM] bf16 ----------
__global__ __launch_bounds__(256) void transW_kernel(const float* __restrict__ W) {
    __shared__ float sm[32][33];
    int v0 = blockIdx.x * 32, k0 = blockIdx.y * 32;
    int tx = threadIdx.x, ty = threadIdx.y;  // 32 x 8
#pragma unroll
    for (int r = 0; r < 4; r++) {
        int k = k0 + ty + r * 8, v = v0 + tx;
        sm[ty + r * 8][tx] = (v < VOC) ? W[(size_t)k * VOC + v] : 0.f;
    }
    __syncthreads();
#pragma unroll
    for (int r = 0; r < 4; r++) {
        int v = v0 + ty + r * 8, k = k0 + tx;
        g_Wt[(size_t)v * DDIM + k] = __float2bfloat16(sm[tx][ty + r * 8]);
    }
}

// ---------------- kernel 1: cp.async mma.sync GEMM ---------------------
// 128x128 tiles, k-chunk 64 (XOR swizzle), 3 stages, 8 warps (2x4),
// warp tile 64x32, 2 CTAs/SM. Dead m-tiles skipped via hlens.
__global__ __launch_bounds__(256, 2)
void mma_gemm_kernel(const float* __restrict__ bias,
                     const int* __restrict__ hlens) {
    extern __shared__ __align__(128) char dynbuf[];
    __shared__ float bias_s[128];
    __shared__ int   slot_s[256];
    __shared__ float redM[128 * 5];
    __shared__ float redS[128 * 5];

    const int n0 = blockIdx.x * 128, m0 = blockIdx.y * 128;
    const int rb0 = m0 / TLEN, rb1 = (m0 + 127) / TLEN;

    const int hl0 = hlens[rb0];
    // dead-tile skip: all 128 rows in one batch, starting at t >= hlen
    if (rb0 == rb1 && (m0 - rb0 * TLEN) >= hl0) return;
    const int hl1 = (rb1 > rb0) ? hlens[rb1] : hl0;

    const uint32_t sbD = (uint32_t)__cvta_generic_to_shared(dynbuf);
    const int tid = threadIdx.x;
    const int lane = tid & 31, wid = tid >> 5;
    const int wm = wid >> 2, wn = wid & 3;

    if (tid < 128) {
        int gc = n0 + tid;
        bias_s[tid]       = (gc < VOC) ? bias[gc] : 0.f;
        slot_s[tid]       = (gc < VOC) ? g_slot[rb0 * VOC + gc] : -1;
        slot_s[128 + tid] = (gc < VOC) ? g_slot[rb1 * VOC + gc] : -1;
    }

    // cp.async mapping: per stage, per operand: 128 rows x 8 chunks of 16B.
    // thread handles rows (tid>>3)+32*i (i=0..3), chunk col tid&7.
    const int crow = tid >> 3;            // base row
    const int cc8  = tid & 7;             // 16B-chunk column
    const uint32_t cxr = (uint32_t)((crow & 7) << 4);   // swizzle (row low bits const per thread)
    const uint32_t cdst = (uint32_t)(crow * 128 + ((cc8 * 16) ^ cxr));
    const __nv_bfloat16* Ab = g_Abf + (size_t)m0 * DDIM;
    const __nv_bfloat16* Bb = g_Wt  + (size_t)n0 * DDIM;

    // prologue: issue stages 0,1
#pragma unroll
    for (int s = 0; s < NSTAGE - 1; s++) {
        uint32_t dst = sbD + s * STAGE_BYTES;
        int k0 = s * KCHUNK;
#pragma unroll
        for (int i = 0; i < 4; i++) {
            CP16(dst + cdst + i * (32 * 128),
                 Ab + (size_t)(crow + 32 * i) * DDIM + k0 + cc8 * 8);
            CP16(dst + TILE_BYTES + cdst + i * (32 * 128),
                 Bb + (size_t)(crow + 32 * i) * DDIM + k0 + cc8 * 8);
        }
        CPCOMMIT();
    }

    float acc[4][16];
#pragma unroll
    for (int i = 0; i < 4; i++)
#pragma unroll
        for (int j = 0; j < 16; j++) acc[i][j] = 0.f;

    // ldsm lane addressing (XOR swizzle)
    const int arow = wm * 64 + (lane & 15);
    const int brow = wn * 32 + (lane & 15);
    const uint32_t axr = (uint32_t)((arow & 7) << 4);
    const uint32_t bxr = (uint32_t)((brow & 7) << 4);
    const uint32_t ahi = (uint32_t)((lane >> 4) << 4);   // 16B col select within half

#pragma unroll
    for (int kc = 0; kc < NKC; kc++) {
        CPWAIT1();            // stage kc complete
        __syncthreads();      // visible to all; prior stage reads done

        int ks = kc + NSTAGE - 1;
        if (ks < NKC) {
            uint32_t dst = sbD + (ks % 3) * STAGE_BYTES;
            int k0 = ks * KCHUNK;
#pragma unroll
            for (int i = 0; i < 4; i++) {
                CP16(dst + cdst + i * (32 * 128),
                     Ab + (size_t)(crow + 32 * i) * DDIM + k0 + cc8 * 8);
                CP16(dst + TILE_BYTES + cdst + i * (32 * 128),
                     Bb + (size_t)(crow + 32 * i) * DDIM + k0 + cc8 * 8);
            }
        }
        CPCOMMIT();           // always commit to keep wait counts exact

        const uint32_t base = sbD + (kc % 3) * STAGE_BYTES;
#pragma unroll
        for (int h = 0; h < 4; h++) {     // four k16 halves of the 128B rows
            const uint32_t acol = ((uint32_t)(h * 32) | ahi) ^ axr;
            const uint32_t bcol = ((uint32_t)(h * 32) | ahi) ^ bxr;
            uint32_t af[4][4], bf[2][4];
#pragma unroll
            for (int mf = 0; mf < 4; mf++)
                ldsm4(af[mf], base + (uint32_t)((arow + mf * 16) * 128) + acol);
#pragma unroll
            for (int jg = 0; jg < 2; jg++)
                ldsm4(bf[jg], base + TILE_BYTES + (uint32_t)((brow + jg * 16) * 128) + bcol);
#pragma unroll
            for (int mf = 0; mf < 4; mf++) {
#pragma unroll
                for (int jg = 0; jg < 2; jg++) {
                    mma16816(&acc[mf][(jg * 2 + 0) * 4], af[mf], bf[jg][0], bf[jg][2]);
                    mma16816(&acc[mf][(jg * 2 + 1) * 4], af[mf], bf[jg][1], bf[jg][3]);
                }
            }
        }
    }

    // ---- epilogue: bias + online max/sumexp + label gather ----
    float biasv[8]; bool validv[8]; int sl0[8], sl1[8];
#pragma unroll
    for (int nf = 0; nf < 4; nf++)
#pragma unroll
        for (int e = 0; e < 2; e++) {
            int idx = nf * 2 + e;
            int c = wn * 32 + nf * 8 + (lane & 3) * 2 + e;
            biasv[idx]  = bias_s[c];
            validv[idx] = (n0 + c) < VOC;
            sl0[idx] = slot_s[c];
            sl1[idx] = slot_s[128 + c];
        }
#pragma unroll
    for (int mf = 0; mf < 4; mf++)
#pragma unroll
        for (int k = 0; k < 16; k++)
            acc[mf][k] += biasv[(k >> 2) * 2 + (k & 1)];

#pragma unroll
    for (int mf = 0; mf < 4; mf++) {
#pragma unroll
        for (int half = 0; half < 2; half++) {
            int r = wm * 64 + mf * 16 + half * 8 + (lane >> 2);
            int grow = m0 + r;
            int bb = (rb1 > rb0 && grow >= rb1 * TLEN) ? 1 : 0;
            int tloc = grow - (bb ? rb1 : rb0) * TLEN;
            bool live = tloc < (bb ? hl1 : hl0);
            float m = -3.4e38f, s = 0.f;
            if (live) {
#pragma unroll
                for (int ci = 0; ci < 8; ci++) {
                    float v = acc[mf][(ci >> 1) * 4 + half * 2 + (ci & 1)];
                    if (validv[ci]) m = fmaxf(m, v);
                }
#pragma unroll
                for (int ci = 0; ci < 8; ci++) {
                    float v = acc[mf][(ci >> 1) * 4 + half * 2 + (ci & 1)];
                    if (validv[ci]) {
                        s += __expf(v - m);
                        int sl = bb ? sl1[ci] : sl0[ci];
                        if (sl >= 0) g_gath[(size_t)grow * GSTRIDE + sl] = v;
                    }
                }
            }
#pragma unroll
            for (int off = 1; off <= 2; off <<= 1) {
                float om = __shfl_xor_sync(~0u, m, off);
                float os = __shfl_xor_sync(~0u, s, off);
                float nm = fmaxf(m, om);
                s = s * __expf(m - nm) + os * __expf(om - nm);
                m = nm;
            }
            if ((lane & 3) == 0) { redM[r * 5 + wn] = m; redS[r * 5 + wn] = s; }
        }
    }
    __syncthreads();
    if (tid < 128) {
        float M = redM[tid * 5 + 0], S = redS[tid * 5 + 0];
#pragma unroll
        for (int w = 1; w < 4; w++) {
            float m2 = redM[tid * 5 + w], s2 = redS[tid * 5 + w];
            float Mn = fmaxf(M, m2);
            S = S * __expf(M - Mn) + s2 * __expf(m2 - Mn);
            M = Mn;
        }
        g_pmax[(m0 + tid) * NTILES + blockIdx.x] = M;
        g_psum[(m0 + tid) * NTILES + blockIdx.x] = S;
    }
}

// ---------------- kernel 2: fused LSE reduce + emit expand -------------
__global__ __launch_bounds__(128) void emit_kernel(const int* __restrict__ ys_pad,
                                                   const int* __restrict__ hlens) {
    const int row = blockIdx.x;
    const int b = row / TLEN;
    if ((row - b * TLEN) >= hlens[b]) return;
    const int tid = threadIdx.x;
    __shared__ float lse_s;
    if (tid < 32) {
        float pm = g_pmax[row * NTILES + tid];
        float ps = g_psum[row * NTILES + tid];
        float M = pm;
#pragma unroll
        for (int o = 16; o; o >>= 1) M = fmaxf(M, __shfl_xor_sync(~0u, M, o));
        float v = ps * __expf(pm - M);
#pragma unroll
        for (int o = 16; o; o >>= 1) v += __shfl_xor_sync(~0u, v, o);
        if (tid == 0) lse_s = M + __logf(v);
    }
    __syncthreads();
    if (tid < NEMIT) {
        int col = (tid == 0) ? 0 : ys_pad[b * LMAX + tid - 1];
        int slot = g_slot[b * VOC + col];
        g_emit[(size_t)row * NEMIT + tid] = g_gath[(size_t)row * GSTRIDE + slot] - lse_s;
    }
}

// ---------------- kernel 3: CTC forward recursion ----------------------
__global__ __launch_bounds__(224) void ctc_kernel(const int* __restrict__ hlens,
                                                  const int* __restrict__ ys_pad,
                                                  const int* __restrict__ ys_lens) {
    const int b = blockIdx.x;
    const int s = threadIdx.x;
    __shared__ float al[2][SEXT + 2];

    const float* eb = g_emit + (size_t)b * TLEN * NEMIT;
    const bool act = s < SEXT;
    const int j = (s & 1) ? ((s >> 1) + 1) : 0;

    bool skip = false;
    if (act && (s & 1) && s >= 3) {
        int cur  = ys_pad[b * LMAX + (s >> 1)];
        int prev = ys_pad[b * LMAX + (s >> 1) - 1];
        skip = (cur != prev);
    }

    if (s < 2) { al[0][s] = NEGV; al[1][s] = NEGV; }
    if (act) al[0][s + 2] = (s < 2) ? eb[j] : NEGV;

    const int hl = hlens[b];
    float e1 = NEGV;
    if (act && hl > 1) e1 = eb[NEMIT + j];
    __syncthreads();

    int p = 0;
    for (int t = 1; t < hl; t++) {
        float e = e1;
        if (act && t + 1 < hl) e1 = eb[(size_t)(t + 1) * NEMIT + j];

        if (act) {
            float a0 = al[p][s + 2];
            float a1 = al[p][s + 1];
            float a2 = skip ? al[p][s] : NEGV;
            float m = fmaxf(a0, fmaxf(a1, a2));
            float w = __expf(a0 - m) + __expf(a1 - m) + __expf(a2 - m);
            al[1 - p][s + 2] = m + __logf(w) + e;
        }
        __syncthreads();
        p ^= 1;
    }

    if (s == 0) {
        int L = ys_lens[b];
        int idx = 2 * L;
        float aL = al[p][idx + 2];
        float aP = al[p][idx + 1];
        float m = fmaxf(aL, aP);
        float loss = -(m + __logf(__expf(aL - m) + __expf(aP - m)));
        if (!isfinite(loss) || loss >= 1e29f) loss = 0.f;
        g_loss[b] = loss;
    }
}

// ---------------- kernel 4: final reduce --------------------------------
__global__ void finalize_kernel(float* __restrict__ out) {
    float sum = 0.f;
    for (int i = 0; i < BATCH; i++) sum += g_loss[i];
    out[0] = sum / (float)BATCH;
}

// ---------------- launch --------------------------------------------------
extern "C" void kernel_launch(void* const* d_in, const int* in_sizes, int n_in,
                              void* d_out, int out_size) {
    const float* hs     = (const float*)d_in[0];
    const float* Wm     = (const float*)d_in[1];
    const float* bias   = (const float*)d_in[2];
    const int* hlens    = (const int*)d_in[3];
    const int* ys_pad   = (const int*)d_in[4];
    const int* ys_lens  = (const int*)d_in[5];
    float* out = (float*)d_out;

    cudaFuncSetAttribute(mma_gemm_kernel,
                         cudaFuncAttributeMaxDynamicSharedMemorySize, DYN_SMEM);

    init_slot_kernel<<<(BATCH * VOC + 255) / 256, 256>>>();
    write_slot_kernel<<<BATCH, 128>>>(ys_pad);
    convA_kernel<<<(NROWS * DDIM / 4 + 255) / 256, 256>>>(hs);
    transW_kernel<<<dim3(VPAD / 32, DDIM / 32), dim3(32, 8)>>>(Wm);

    dim3 gemm_grid(NTILES, NROWS / 128);  // (32, 100)
    mma_gemm_kernel<<<gemm_grid, 256, DYN_SMEM>>>(bias, hlens);

    emit_kernel<<<NROWS, 128>>>(ys_pad, hlens);
    ctc_kernel<<<BATCH, 224>>>(hlens, ys_pad, ys_lens);
    finalize_kernel<<<1, 1>>>(out);
}

// round 10
// speedup vs baseline: 1.6881x; 1.0429x over previous
#include <cuda_runtime.h>
#include <cuda_bf16.h>
#include <math.h>
#include <stdint.h>

#define BATCH 16
#define TLEN 800
#define DDIM 512
#define VOC 4000
#define VPAD 4096
#define LMAX 100
#define SEXT 201
#define NEMIT 101
#define NROWS (BATCH * TLEN)
#define NTILES 32
#define GSTRIDE 104
#define NEGV (-1e30f)

#define KCHUNK 64
#define NKC 8                 // 512 / 64
#define TILE_BYTES 16384      // 128 rows * 128 B (XOR swizzle)
#define STAGE_BYTES 32768     // A tile + B tile
#define NSTAGE 3
#define DYN_SMEM (NSTAGE * STAGE_BYTES)   // 98304

// ---------------- device scratch ----------------
__device__ __align__(16) __nv_bfloat16 g_Abf[(size_t)NROWS * DDIM];  // compacted
__device__ __align__(16) __nv_bfloat16 g_Wt[(size_t)VPAD * DDIM];
__device__ float g_pmax[NROWS * NTILES];
__device__ float g_psum[NROWS * NTILES];
__device__ float g_gath[(size_t)NROWS * GSTRIDE];
__device__ float g_emit[(size_t)NROWS * NEMIT];   // compacted rows
__device__ int   g_slot[BATCH * VOC];
__device__ float g_loss[BATCH];
__device__ int   g_off[BATCH + 1];                // live-row prefix sums
__device__ int   g_nlive;
__device__ int   g_rowinfo[NROWS];                // compacted row -> (b<<16)|t

// ---------------- PTX helpers (compute_103-legal) ----------------------
__device__ __forceinline__ void ldsm4(uint32_t* r, uint32_t addr) {
    asm volatile("ldmatrix.sync.aligned.m8n8.x4.shared.b16 {%0,%1,%2,%3}, [%4];"
                 : "=r"(r[0]), "=r"(r[1]), "=r"(r[2]), "=r"(r[3]) : "r"(addr));
}
__device__ __forceinline__ void mma16816(float* d, const uint32_t* a,
                                         uint32_t b0, uint32_t b1) {
    asm volatile(
        "mma.sync.aligned.m16n8k16.row.col.f32.bf16.bf16.f32 "
        "{%0,%1,%2,%3}, {%4,%5,%6,%7}, {%8,%9}, {%0,%1,%2,%3};"
        : "+f"(d[0]), "+f"(d[1]), "+f"(d[2]), "+f"(d[3])
        : "r"(a[0]), "r"(a[1]), "r"(a[2]), "r"(a[3]), "r"(b0), "r"(b1));
}
#define CP16(dst, src) \
    asm volatile("cp.async.cg.shared.global [%0], [%1], 16;" :: "r"(dst), "l"(src))
#define CPCOMMIT() asm volatile("cp.async.commit_group;")
#define CPWAIT1()  asm volatile("cp.async.wait_group 1;")

// ---------------- kernel 0: slot map + prefix + rowinfo ----------------
__global__ void init_slot_kernel() {
    int i = blockIdx.x * blockDim.x + threadIdx.x;
    if (i < BATCH * VOC) g_slot[i] = -1;
}
__global__ void write_slot_kernel(const int* __restrict__ ys_pad) {
    int b = blockIdx.x;
    int j = threadIdx.x;
    if (j < LMAX) g_slot[b * VOC + ys_pad[b * LMAX + j]] = j + 1;
    if (j == LMAX) g_slot[b * VOC + 0] = 0;
}
__global__ void prefix_kernel(const int* __restrict__ hlens) {
    int s = 0;
    g_off[0] = 0;
#pragma unroll
    for (int i = 0; i < BATCH; i++) { s += hlens[i]; g_off[i + 1] = s; }
    g_nlive = s;
}
__global__ __launch_bounds__(256) void rowinfo_kernel() {
    int r = blockIdx.x * 256 + threadIdx.x;
    if (r >= NROWS) return;
    int info;
    if (r < g_nlive) {
        int b = 0;
#pragma unroll
        for (int i = 1; i <= BATCH; i++)
            if (r >= g_off[i]) b = i;
        info = (b << 16) | (r - g_off[b]);
    } else {
        info = 0xFFFF;   // dead marker (b=0, t=0xFFFF)
    }
    g_rowinfo[r] = info;
}

// ---------------- kernel 0c: convert A to bf16, compacted --------------
__global__ __launch_bounds__(256) void convA_kernel(const float* __restrict__ src,
                                                    const int* __restrict__ hlens) {
    int r = blockIdx.x * 8 + (threadIdx.x >> 5);   // source row
    int lane = threadIdx.x & 31;
    int b = r / TLEN, t = r - b * TLEN;
    if (t >= hlens[b]) return;
    int dst = g_off[b] + t;
    const float* p = src + (size_t)r * DDIM;
    __nv_bfloat16* q = g_Abf + (size_t)dst * DDIM;
#pragma unroll
    for (int i = 0; i < 4; i++) {
        float4 v = *(const float4*)(p + lane * 4 + i * 128);
        *(__nv_bfloat162*)(q + lane * 4 + i * 128)     = __floats2bfloat162_rn(v.x, v.y);
        *(__nv_bfloat162*)(q + lane * 4 + i * 128 + 2) = __floats2bfloat162_rn(v.z, v.w);
    }
}

// ---------------- kernel 0d: transpose W -> [VPAD, DDIM] bf16 ----------
__global__ __launch_bounds__(256) void transW_kernel(const float* __restrict__ W) {
    __shared__ float sm[32][33];
    int v0 = blockIdx.x * 32, k0 = blockIdx.y * 32;
    int tx = threadIdx.x, ty = threadIdx.y;  // 32 x 8
#pragma unroll
    for (int r = 0; r < 4; r++) {
        int k = k0 + ty + r * 8, v = v0 + tx;
        sm[ty + r * 8][tx] = (v < VOC) ? W[(size_t)k * VOC + v] : 0.f;
    }
    __syncthreads();
#pragma unroll
    for (int r = 0; r < 4; r++) {
        int v = v0 + ty + r * 8, k = k0 + tx;
        g_Wt[(size_t)v * DDIM + k] = __float2bfloat16(sm[tx][ty + r * 8]);
    }
}

// ---------------- kernel 1: cp.async mma.sync GEMM (compacted M) -------
__global__ __launch_bounds__(256, 2)
void mma_gemm_kernel(const float* __restrict__ bias) {
    extern __shared__ __align__(128) char dynbuf[];
    __shared__ float bias_s[128];
    __shared__ int   slot_s[256];
    __shared__ int   info_s[128];
    __shared__ float redM[128 * 5];
    __shared__ float redS[128 * 5];

    const int n0 = blockIdx.x * 128, m0 = blockIdx.y * 128;
    const int nlive = g_nlive;
    if (m0 >= nlive) return;   // compacted: all dead tiles are a suffix

    const int rb0 = g_rowinfo[m0] >> 16;
    const int rlast = (m0 + 127 < nlive) ? (m0 + 127) : (nlive - 1);
    const int rb1 = g_rowinfo[rlast] >> 16;

    const uint32_t sbD = (uint32_t)__cvta_generic_to_shared(dynbuf);
    const int tid = threadIdx.x;
    const int lane = tid & 31, wid = tid >> 5;
    const int wm = wid >> 2, wn = wid & 3;

    if (tid < 128) {
        int gc = n0 + tid;
        bias_s[tid]       = (gc < VOC) ? bias[gc] : 0.f;
        slot_s[tid]       = (gc < VOC) ? g_slot[rb0 * VOC + gc] : -1;
        slot_s[128 + tid] = (gc < VOC) ? g_slot[rb1 * VOC + gc] : -1;
        info_s[tid]       = g_rowinfo[m0 + tid];
    }

    // cp.async mapping: 128 rows x 8 chunks of 16B per operand per stage
    const int crow = tid >> 3;
    const int cc8  = tid & 7;
    const uint32_t cxr = (uint32_t)((crow & 7) << 4);
    const uint32_t cdst = (uint32_t)(crow * 128 + ((cc8 * 16) ^ cxr));
    const __nv_bfloat16* Ab = g_Abf + (size_t)m0 * DDIM;
    const __nv_bfloat16* Bb = g_Wt  + (size_t)n0 * DDIM;

#pragma unroll
    for (int s = 0; s < NSTAGE - 1; s++) {
        uint32_t dst = sbD + s * STAGE_BYTES;
        int k0 = s * KCHUNK;
#pragma unroll
        for (int i = 0; i < 4; i++) {
            CP16(dst + cdst + i * (32 * 128),
                 Ab + (size_t)(crow + 32 * i) * DDIM + k0 + cc8 * 8);
            CP16(dst + TILE_BYTES + cdst + i * (32 * 128),
                 Bb + (size_t)(crow + 32 * i) * DDIM + k0 + cc8 * 8);
        }
        CPCOMMIT();
    }

    float acc[4][16];
#pragma unroll
    for (int i = 0; i < 4; i++)
#pragma unroll
        for (int j = 0; j < 16; j++) acc[i][j] = 0.f;

    const int arow = wm * 64 + (lane & 15);
    const int brow = wn * 32 + (lane & 15);
    const uint32_t axr = (uint32_t)((arow & 7) << 4);
    const uint32_t bxr = (uint32_t)((brow & 7) << 4);
    const uint32_t ahi = (uint32_t)((lane >> 4) << 4);

#pragma unroll
    for (int kc = 0; kc < NKC; kc++) {
        CPWAIT1();
        __syncthreads();

        int ks = kc + NSTAGE - 1;
        if (ks < NKC) {
            uint32_t dst = sbD + (ks % 3) * STAGE_BYTES;
            int k0 = ks * KCHUNK;
#pragma unroll
            for (int i = 0; i < 4; i++) {
                CP16(dst + cdst + i * (32 * 128),
                     Ab + (size_t)(crow + 32 * i) * DDIM + k0 + cc8 * 8);
                CP16(dst + TILE_BYTES + cdst + i * (32 * 128),
                     Bb + (size_t)(crow + 32 * i) * DDIM + k0 + cc8 * 8);
            }
        }
        CPCOMMIT();

        const uint32_t base = sbD + (kc % 3) * STAGE_BYTES;
#pragma unroll
        for (int h = 0; h < 4; h++) {
            const uint32_t acol = ((uint32_t)(h * 32) | ahi) ^ axr;
            const uint32_t bcol = ((uint32_t)(h * 32) | ahi) ^ bxr;
            uint32_t af[4][4], bf[2][4];
#pragma unroll
            for (int mf = 0; mf < 4; mf++)
                ldsm4(af[mf], base + (uint32_t)((arow + mf * 16) * 128) + acol);
#pragma unroll
            for (int jg = 0; jg < 2; jg++)
                ldsm4(bf[jg], base + TILE_BYTES + (uint32_t)((brow + jg * 16) * 128) + bcol);
#pragma unroll
            for (int mf = 0; mf < 4; mf++) {
#pragma unroll
                for (int jg = 0; jg < 2; jg++) {
                    mma16816(&acc[mf][(jg * 2 + 0) * 4], af[mf], bf[jg][0], bf[jg][2]);
                    mma16816(&acc[mf][(jg * 2 + 1) * 4], af[mf], bf[jg][1], bf[jg][3]);
                }
            }
        }
    }

    // ---- epilogue: bias + online max/sumexp + label gather ----
    float biasv[8]; bool validv[8]; int sl0[8], sl1[8];
#pragma unroll
    for (int nf = 0; nf < 4; nf++)
#pragma unroll
        for (int e = 0; e < 2; e++) {
            int idx = nf * 2 + e;
            int c = wn * 32 + nf * 8 + (lane & 3) * 2 + e;
            biasv[idx]  = bias_s[c];
            validv[idx] = (n0 + c) < VOC;
            sl0[idx] = slot_s[c];
            sl1[idx] = slot_s[128 + c];
        }
#pragma unroll
    for (int mf = 0; mf < 4; mf++)
#pragma unroll
        for (int k = 0; k < 16; k++)
            acc[mf][k] += biasv[(k >> 2) * 2 + (k & 1)];

#pragma unroll
    for (int mf = 0; mf < 4; mf++) {
#pragma unroll
        for (int half = 0; half < 2; half++) {
            int r = wm * 64 + mf * 16 + half * 8 + (lane >> 2);
            int grow = m0 + r;
            bool live = grow < nlive;
            int bb = ((info_s[r] >> 16) != rb0) ? 1 : 0;
            float m = -3.4e38f, s = 0.f;
            if (live) {
#pragma unroll
                for (int ci = 0; ci < 8; ci++) {
                    float v = acc[mf][(ci >> 1) * 4 + half * 2 + (ci & 1)];
                    if (validv[ci]) m = fmaxf(m, v);
                }
#pragma unroll
                for (int ci = 0; ci < 8; ci++) {
                    float v = acc[mf][(ci >> 1) * 4 + half * 2 + (ci & 1)];
                    if (validv[ci]) {
                        s += __expf(v - m);
                        int sl = bb ? sl1[ci] : sl0[ci];
                        if (sl >= 0) g_gath[(size_t)grow * GSTRIDE + sl] = v;
                    }
                }
            }
#pragma unroll
            for (int off = 1; off <= 2; off <<= 1) {
                float om = __shfl_xor_sync(~0u, m, off);
                float os = __shfl_xor_sync(~0u, s, off);
                float nm = fmaxf(m, om);
                s = s * __expf(m - nm) + os * __expf(om - nm);
                m = nm;
            }
            if ((lane & 3) == 0) { redM[r * 5 + wn] = m; redS[r * 5 + wn] = s; }
        }
    }
    __syncthreads();
    if (tid < 128) {
        float M = redM[tid * 5 + 0], S = redS[tid * 5 + 0];
#pragma unroll
        for (int w = 1; w < 4; w++) {
            float m2 = redM[tid * 5 + w], s2 = redS[tid * 5 + w];
            float Mn = fmaxf(M, m2);
            S = S * __expf(M - Mn) + s2 * __expf(m2 - Mn);
            M = Mn;
        }
        g_pmax[(m0 + tid) * NTILES + blockIdx.x] = M;
        g_psum[(m0 + tid) * NTILES + blockIdx.x] = S;
    }
}

// ---------------- kernel 2: fused LSE reduce + emit expand -------------
__global__ __launch_bounds__(128) void emit_kernel(const int* __restrict__ ys_pad) {
    const int row = blockIdx.x;          // compacted row
    if (row >= g_nlive) return;
    const int b = g_rowinfo[row] >> 16;
    const int tid = threadIdx.x;
    __shared__ float lse_s;
    if (tid < 32) {
        float pm = g_pmax[row * NTILES + tid];
        float ps = g_psum[row * NTILES + tid];
        float M = pm;
#pragma unroll
        for (int o = 16; o; o >>= 1) M = fmaxf(M, __shfl_xor_sync(~0u, M, o));
        float v = ps * __expf(pm - M);
#pragma unroll
        for (int o = 16; o; o >>= 1) v += __shfl_xor_sync(~0u, v, o);
        if (tid == 0) lse_s = M + __logf(v);
    }
    __syncthreads();
    if (tid < NEMIT) {
        int col = (tid == 0) ? 0 : ys_pad[b * LMAX + tid - 1];
        int slot = g_slot[b * VOC + col];
        g_emit[(size_t)row * NEMIT + tid] = g_gath[(size_t)row * GSTRIDE + slot] - lse_s;
    }
}

// ---------------- kernel 3: CTC forward recursion ----------------------
__global__ __launch_bounds__(224) void ctc_kernel(const int* __restrict__ hlens,
                                                  const int* __restrict__ ys_pad,
                                                  const int* __restrict__ ys_lens) {
    const int b = blockIdx.x;
    const int s = threadIdx.x;
    __shared__ float al[2][SEXT + 2];

    const float* eb = g_emit + (size_t)g_off[b] * NEMIT;   // compacted offset
    const bool act = s < SEXT;
    const int j = (s & 1) ? ((s >> 1) + 1) : 0;

    bool skip = false;
    if (act && (s & 1) && s >= 3) {
        int cur  = ys_pad[b * LMAX + (s >> 1)];
        int prev = ys_pad[b * LMAX + (s >> 1) - 1];
        skip = (cur != prev);
    }

    if (s < 2) { al[0][s] = NEGV; al[1][s] = NEGV; }
    if (act) al[0][s + 2] = (s < 2) ? eb[j] : NEGV;

    const int hl = hlens[b];
    float e1 = NEGV;
    if (act && hl > 1) e1 = eb[NEMIT + j];
    __syncthreads();

    int p = 0;
    for (int t = 1; t < hl; t++) {
        float e = e1;
        if (act && t + 1 < hl) e1 = eb[(size_t)(t + 1) * NEMIT + j];

        if (act) {
            float a0 = al[p][s + 2];
            float a1 = al[p][s + 1];
            float a2 = skip ? al[p][s] : NEGV;
            float m = fmaxf(a0, fmaxf(a1, a2));
            float w = __expf(a0 - m) + __expf(a1 - m) + __expf(a2 - m);
            al[1 - p][s + 2] = m + __logf(w) + e;
        }
        __syncthreads();
        p ^= 1;
    }

    if (s == 0) {
        int L = ys_lens[b];
        int idx = 2 * L;
        float aL = al[p][idx + 2];
        float aP = al[p][idx + 1];
        float m = fmaxf(aL, aP);
        float loss = -(m + __logf(__expf(aL - m) + __expf(aP - m)));
        if (!isfinite(loss) || loss >= 1e29f) loss = 0.f;
        g_loss[b] = loss;
    }
}

// ---------------- kernel 4: final reduce --------------------------------
__global__ void finalize_kernel(float* __restrict__ out) {
    float sum = 0.f;
    for (int i = 0; i < BATCH; i++) sum += g_loss[i];
    out[0] = sum / (float)BATCH;
}

// ---------------- launch --------------------------------------------------
extern "C" void kernel_launch(void* const* d_in, const int* in_sizes, int n_in,
                              void* d_out, int out_size) {
    const float* hs     = (const float*)d_in[0];
    const float* Wm     = (const float*)d_in[1];
    const float* bias   = (const float*)d_in[2];
    const int* hlens    = (const int*)d_in[3];
    const int* ys_pad   = (const int*)d_in[4];
    const int* ys_lens  = (const int*)d_in[5];
    float* out = (float*)d_out;

    cudaFuncSetAttribute(mma_gemm_kernel,
                         cudaFuncAttributeMaxDynamicSharedMemorySize, DYN_SMEM);

    init_slot_kernel<<<(BATCH * VOC + 255) / 256, 256>>>();
    write_slot_kernel<<<BATCH, 128>>>(ys_pad);
    prefix_kernel<<<1, 1>>>(hlens);
    rowinfo_kernel<<<(NROWS + 255) / 256, 256>>>();
    convA_kernel<<<NROWS / 8, 256>>>(hs, hlens);
    transW_kernel<<<dim3(VPAD / 32, DDIM / 32), dim3(32, 8)>>>(Wm);

    dim3 gemm_grid(NTILES, NROWS / 128);  // (32, 100); suffix tiles early-exit
    mma_gemm_kernel<<<gemm_grid, 256, DYN_SMEM>>>(bias);

    emit_kernel<<<NROWS, 128>>>(ys_pad);
    ctc_kernel<<<BATCH, 224>>>(hlens, ys_pad, ys_lens);
    finalize_kernel<<<1, 1>>>(out);
}

// round 11
// speedup vs baseline: 1.7049x; 1.0099x over previous
#include <cuda_runtime.h>
#include <cuda_bf16.h>
#include <math.h>
#include <stdint.h>

#define BATCH 16
#define TLEN 800
#define DDIM 512
#define VOC 4000
#define VPAD 4096
#define LMAX 100
#define SEXT 201
#define NEMIT 101
#define NROWS (BATCH * TLEN)
#define NTILES 32
#define GSTRIDE 104
#define NEGV (-1e30f)

#define KCHUNK 64
#define NKC 8                 // 512 / 64
#define TILE_BYTES 16384      // 128 rows * 128 B (XOR swizzle)
#define STAGE_BYTES 32768     // A tile + B tile
#define NSTAGE 3
#define DYN_SMEM (NSTAGE * STAGE_BYTES)   // 98304

// prep kernel block ranges
#define PREP_CONV   1600      // NROWS / 8
#define PREP_TRANSW 2048      // (VPAD/32) * (DDIM/32)
#define PREP_INIT   250       // BATCH*VOC / 256
#define PREP_BLOCKS (PREP_CONV + PREP_TRANSW + PREP_INIT)

// ---------------- device scratch ----------------
__device__ __align__(16) __nv_bfloat16 g_Abf[(size_t)NROWS * DDIM];  // compacted
__device__ __align__(16) __nv_bfloat16 g_Wt[(size_t)VPAD * DDIM];
__device__ float g_pmax[NROWS * NTILES];
__device__ float g_psum[NROWS * NTILES];
__device__ float g_gath[(size_t)NROWS * GSTRIDE];
__device__ float g_emit[(size_t)NROWS * NEMIT];   // compacted rows
__device__ int   g_slot[BATCH * VOC];
__device__ float g_loss[BATCH];

// ---------------- inline index helpers ---------------------------------
__device__ __forceinline__ int sum_hlens(const int* __restrict__ hlens) {
    int s = 0;
#pragma unroll
    for (int i = 0; i < BATCH; i++) s += __ldg(&hlens[i]);
    return s;
}
__device__ __forceinline__ int batch_of(int row, const int* __restrict__ hlens) {
    int off = 0, b = 0;
#pragma unroll
    for (int i = 0; i < BATCH; i++) {
        int nx = off + __ldg(&hlens[i]);
        if (row >= nx) { off = nx; b = i + 1; }
    }
    return b;
}
__device__ __forceinline__ int off_of_batch(int b, const int* __restrict__ hlens) {
    int off = 0;
#pragma unroll
    for (int i = 0; i < BATCH; i++)
        if (i < b) off += __ldg(&hlens[i]);
    return off;
}

// ---------------- PTX helpers (compute_103-legal) ----------------------
__device__ __forceinline__ void ldsm4(uint32_t* r, uint32_t addr) {
    asm volatile("ldmatrix.sync.aligned.m8n8.x4.shared.b16 {%0,%1,%2,%3}, [%4];"
                 : "=r"(r[0]), "=r"(r[1]), "=r"(r[2]), "=r"(r[3]) : "r"(addr));
}
__device__ __forceinline__ void mma16816(float* d, const uint32_t* a,
                                         uint32_t b0, uint32_t b1) {
    asm volatile(
        "mma.sync.aligned.m16n8k16.row.col.f32.bf16.bf16.f32 "
        "{%0,%1,%2,%3}, {%4,%5,%6,%7}, {%8,%9}, {%0,%1,%2,%3};"
        : "+f"(d[0]), "+f"(d[1]), "+f"(d[2]), "+f"(d[3])
        : "r"(a[0]), "r"(a[1]), "r"(a[2]), "r"(a[3]), "r"(b0), "r"(b1));
}
#define CP16(dst, src) \
    asm volatile("cp.async.cg.shared.global [%0], [%1], 16;" :: "r"(dst), "l"(src))
#define CPCOMMIT() asm volatile("cp.async.commit_group;")
#define CPWAIT1()  asm volatile("cp.async.wait_group 1;")

// ---------------- kernel 0: fused prep (convA + transW + slot init) ----
__global__ __launch_bounds__(256) void prep_kernel(const float* __restrict__ src,
                                                   const float* __restrict__ W,
                                                   const int* __restrict__ hlens) {
    const int bid = blockIdx.x;
    const int tid = threadIdx.x;

    if (bid < PREP_CONV) {
        // ---- convA: fp32 -> bf16, row-compacted ----
        int r = bid * 8 + (tid >> 5);
        int lane = tid & 31;
        int b = r / TLEN, t = r - b * TLEN;
        if (t >= __ldg(&hlens[b])) return;
        int dst = off_of_batch(b, hlens) + t;
        const float* p = src + (size_t)r * DDIM;
        __nv_bfloat16* q = g_Abf + (size_t)dst * DDIM;
#pragma unroll
        for (int i = 0; i < 4; i++) {
            float4 v = *(const float4*)(p + lane * 4 + i * 128);
            *(__nv_bfloat162*)(q + lane * 4 + i * 128)     = __floats2bfloat162_rn(v.x, v.y);
            *(__nv_bfloat162*)(q + lane * 4 + i * 128 + 2) = __floats2bfloat162_rn(v.z, v.w);
        }
    } else if (bid < PREP_CONV + PREP_TRANSW) {
        // ---- transW: W[k][v] -> g_Wt[v][k] bf16 ----
        __shared__ float sm[32][33];
        int idx = bid - PREP_CONV;
        int v0 = (idx & 127) * 32, k0 = (idx >> 7) * 32;
        int tx = tid & 31, ty = tid >> 5;   // 32 x 8
#pragma unroll
        for (int r = 0; r < 4; r++) {
            int k = k0 + ty + r * 8, v = v0 + tx;
            sm[ty + r * 8][tx] = (v < VOC) ? W[(size_t)k * VOC + v] : 0.f;
        }
        __syncthreads();
#pragma unroll
        for (int r = 0; r < 4; r++) {
            int v = v0 + ty + r * 8, k = k0 + tx;
            g_Wt[(size_t)v * DDIM + k] = __float2bfloat16(sm[tx][ty + r * 8]);
        }
    } else {
        // ---- slot map init ----
        int i = (bid - PREP_CONV - PREP_TRANSW) * 256 + tid;
        if (i < BATCH * VOC) g_slot[i] = -1;
    }
}

// ---------------- kernel 0b: write label slots -------------------------
__global__ void write_slot_kernel(const int* __restrict__ ys_pad) {
    int b = blockIdx.x;
    int j = threadIdx.x;
    if (j < LMAX) g_slot[b * VOC + ys_pad[b * LMAX + j]] = j + 1;
    if (j == LMAX) g_slot[b * VOC + 0] = 0;
}

// ---------------- kernel 1: cp.async mma.sync GEMM (compacted M) -------
__global__ __launch_bounds__(256, 2)
void mma_gemm_kernel(const float* __restrict__ bias,
                     const int* __restrict__ hlens) {
    extern __shared__ __align__(128) char dynbuf[];
    __shared__ float bias_s[128];
    __shared__ int   slot_s[256];
    __shared__ int   info_s[128];
    __shared__ float redM[128 * 5];
    __shared__ float redS[128 * 5];

    const int n0 = blockIdx.x * 128, m0 = blockIdx.y * 128;
    const int nlive = sum_hlens(hlens);
    if (m0 >= nlive) return;   // compacted: dead tiles are a suffix

    const int rb0 = batch_of(m0, hlens);
    const int rlast = (m0 + 127 < nlive) ? (m0 + 127) : (nlive - 1);
    const int rb1 = batch_of(rlast, hlens);

    const uint32_t sbD = (uint32_t)__cvta_generic_to_shared(dynbuf);
    const int tid = threadIdx.x;
    const int lane = tid & 31, wid = tid >> 5;
    const int wm = wid >> 2, wn = wid & 3;

    // cp.async mapping: 128 rows x 8 chunks of 16B per operand per stage
    const int crow = tid >> 3;
    const int cc8  = tid & 7;
    const uint32_t cxr = (uint32_t)((crow & 7) << 4);
    const uint32_t cdst = (uint32_t)(crow * 128 + ((cc8 * 16) ^ cxr));
    const __nv_bfloat16* Ab = g_Abf + (size_t)m0 * DDIM;
    const __nv_bfloat16* Bb = g_Wt  + (size_t)n0 * DDIM;

    // prologue first: get loads in flight before index bookkeeping
#pragma unroll
    for (int s = 0; s < NSTAGE - 1; s++) {
        uint32_t dst = sbD + s * STAGE_BYTES;
        int k0 = s * KCHUNK;
#pragma unroll
        for (int i = 0; i < 4; i++) {
            CP16(dst + cdst + i * (32 * 128),
                 Ab + (size_t)(crow + 32 * i) * DDIM + k0 + cc8 * 8);
            CP16(dst + TILE_BYTES + cdst + i * (32 * 128),
                 Bb + (size_t)(crow + 32 * i) * DDIM + k0 + cc8 * 8);
        }
        CPCOMMIT();
    }

    if (tid < 128) {
        int gc = n0 + tid;
        bias_s[tid]       = (gc < VOC) ? bias[gc] : 0.f;
        slot_s[tid]       = (gc < VOC) ? g_slot[rb0 * VOC + gc] : -1;
        slot_s[128 + tid] = (gc < VOC) ? g_slot[rb1 * VOC + gc] : -1;
        info_s[tid]       = batch_of(m0 + tid, hlens);
    }

    float acc[4][16];
#pragma unroll
    for (int i = 0; i < 4; i++)
#pragma unroll
        for (int j = 0; j < 16; j++) acc[i][j] = 0.f;

    const int arow = wm * 64 + (lane & 15);
    const int brow = wn * 32 + (lane & 15);
    const uint32_t axr = (uint32_t)((arow & 7) << 4);
    const uint32_t bxr = (uint32_t)((brow & 7) << 4);
    const uint32_t ahi = (uint32_t)((lane >> 4) << 4);

#pragma unroll
    for (int kc = 0; kc < NKC; kc++) {
        CPWAIT1();
        __syncthreads();   // stage kc visible (also publishes bias/slot/info smem)

        int ks = kc + NSTAGE - 1;
        if (ks < NKC) {
            uint32_t dst = sbD + (ks % 3) * STAGE_BYTES;
            int k0 = ks * KCHUNK;
#pragma unroll
            for (int i = 0; i < 4; i++) {
                CP16(dst + cdst + i * (32 * 128),
                     Ab + (size_t)(crow + 32 * i) * DDIM + k0 + cc8 * 8);
                CP16(dst + TILE_BYTES + cdst + i * (32 * 128),
                     Bb + (size_t)(crow + 32 * i) * DDIM + k0 + cc8 * 8);
            }
        }
        CPCOMMIT();

        const uint32_t base = sbD + (kc % 3) * STAGE_BYTES;
#pragma unroll
        for (int h = 0; h < 4; h++) {
            const uint32_t acol = ((uint32_t)(h * 32) | ahi) ^ axr;
            const uint32_t bcol = ((uint32_t)(h * 32) | ahi) ^ bxr;
            uint32_t af[4][4], bf[2][4];
#pragma unroll
            for (int mf = 0; mf < 4; mf++)
                ldsm4(af[mf], base + (uint32_t)((arow + mf * 16) * 128) + acol);
#pragma unroll
            for (int jg = 0; jg < 2; jg++)
                ldsm4(bf[jg], base + TILE_BYTES + (uint32_t)((brow + jg * 16) * 128) + bcol);
#pragma unroll
            for (int mf = 0; mf < 4; mf++) {
#pragma unroll
                for (int jg = 0; jg < 2; jg++) {
                    mma16816(&acc[mf][(jg * 2 + 0) * 4], af[mf], bf[jg][0], bf[jg][2]);
                    mma16816(&acc[mf][(jg * 2 + 1) * 4], af[mf], bf[jg][1], bf[jg][3]);
                }
            }
        }
    }

    // ---- epilogue: bias + online max/sumexp + label gather ----
    float biasv[8]; bool validv[8]; int sl0[8], sl1[8];
#pragma unroll
    for (int nf = 0; nf < 4; nf++)
#pragma unroll
        for (int e = 0; e < 2; e++) {
            int idx = nf * 2 + e;
            int c = wn * 32 + nf * 8 + (lane & 3) * 2 + e;
            biasv[idx]  = bias_s[c];
            validv[idx] = (n0 + c) < VOC;
            sl0[idx] = slot_s[c];
            sl1[idx] = slot_s[128 + c];
        }
#pragma unroll
    for (int mf = 0; mf < 4; mf++)
#pragma unroll
        for (int k = 0; k < 16; k++)
            acc[mf][k] += biasv[(k >> 2) * 2 + (k & 1)];

#pragma unroll
    for (int mf = 0; mf < 4; mf++) {
#pragma unroll
        for (int half = 0; half < 2; half++) {
            int r = wm * 64 + mf * 16 + half * 8 + (lane >> 2);
            int grow = m0 + r;
            bool live = grow < nlive;
            int bb = (info_s[r] != rb0) ? 1 : 0;
            float m = -3.4e38f, s = 0.f;
            if (live) {
#pragma unroll
                for (int ci = 0; ci < 8; ci++) {
                    float v = acc[mf][(ci >> 1) * 4 + half * 2 + (ci & 1)];
                    if (validv[ci]) m = fmaxf(m, v);
                }
#pragma unroll
                for (int ci = 0; ci < 8; ci++) {
                    float v = acc[mf][(ci >> 1) * 4 + half * 2 + (ci & 1)];
                    if (validv[ci]) {
                        s += __expf(v - m);
                        int sl = bb ? sl1[ci] : sl0[ci];
                        if (sl >= 0) g_gath[(size_t)grow * GSTRIDE + sl] = v;
                    }
                }
            }
#pragma unroll
            for (int off = 1; off <= 2; off <<= 1) {
                float om = __shfl_xor_sync(~0u, m, off);
                float os = __shfl_xor_sync(~0u, s, off);
                float nm = fmaxf(m, om);
                s = s * __expf(m - nm) + os * __expf(om - nm);
                m = nm;
            }
            if ((lane & 3) == 0) { redM[r * 5 + wn] = m; redS[r * 5 + wn] = s; }
        }
    }
    __syncthreads();
    if (tid < 128) {
        float M = redM[tid * 5 + 0], S = redS[tid * 5 + 0];
#pragma unroll
        for (int w = 1; w < 4; w++) {
            float m2 = redM[tid * 5 + w], s2 = redS[tid * 5 + w];
            float Mn = fmaxf(M, m2);
            S = S * __expf(M - Mn) + s2 * __expf(m2 - Mn);
            M = Mn;
        }
        g_pmax[(m0 + tid) * NTILES + blockIdx.x] = M;
        g_psum[(m0 + tid) * NTILES + blockIdx.x] = S;
    }
}

// ---------------- kernel 2: fused LSE reduce + emit expand -------------
__global__ __launch_bounds__(128) void emit_kernel(const int* __restrict__ ys_pad,
                                                   const int* __restrict__ hlens) {
    const int row = blockIdx.x;          // compacted row
    const int nlive = sum_hlens(hlens);
    if (row >= nlive) return;
    const int b = batch_of(row, hlens);
    const int tid = threadIdx.x;
    __shared__ float lse_s;
    if (tid < 32) {
        float pm = g_pmax[row * NTILES + tid];
        float ps = g_psum[row * NTILES + tid];
        float M = pm;
#pragma unroll
        for (int o = 16; o; o >>= 1) M = fmaxf(M, __shfl_xor_sync(~0u, M, o));
        float v = ps * __expf(pm - M);
#pragma unroll
        for (int o = 16; o; o >>= 1) v += __shfl_xor_sync(~0u, v, o);
        if (tid == 0) lse_s = M + __logf(v);
    }
    __syncthreads();
    if (tid < NEMIT) {
        int col = (tid == 0) ? 0 : ys_pad[b * LMAX + tid - 1];
        int slot = g_slot[b * VOC + col];
        g_emit[(size_t)row * NEMIT + tid] = g_gath[(size_t)row * GSTRIDE + slot] - lse_s;
    }
}

// ---------------- kernel 3: CTC forward recursion ----------------------
__global__ __launch_bounds__(224) void ctc_kernel(const int* __restrict__ hlens,
                                                  const int* __restrict__ ys_pad,
                                                  const int* __restrict__ ys_lens) {
    const int b = blockIdx.x;
    const int s = threadIdx.x;
    __shared__ float al[2][SEXT + 2];

    const int roff = off_of_batch(b, hlens);
    const float* eb = g_emit + (size_t)roff * NEMIT;
    const bool act = s < SEXT;
    const int j = (s & 1) ? ((s >> 1) + 1) : 0;

    bool skip = false;
    if (act && (s & 1) && s >= 3) {
        int cur  = ys_pad[b * LMAX + (s >> 1)];
        int prev = ys_pad[b * LMAX + (s >> 1) - 1];
        skip = (cur != prev);
    }

    if (s < 2) { al[0][s] = NEGV; al[1][s] = NEGV; }
    if (act) al[0][s + 2] = (s < 2) ? eb[j] : NEGV;

    const int hl = hlens[b];
    float e1 = NEGV;
    if (act && hl > 1) e1 = eb[NEMIT + j];
    __syncthreads();

    int p = 0;
    for (int t = 1; t < hl; t++) {
        float e = e1;
        if (act && t + 1 < hl) e1 = eb[(size_t)(t + 1) * NEMIT + j];

        if (act) {
            float a0 = al[p][s + 2];
            float a1 = al[p][s + 1];
            float a2 = skip ? al[p][s] : NEGV;
            float m = fmaxf(a0, fmaxf(a1, a2));
            float w = __expf(a0 - m) + __expf(a1 - m) + __expf(a2 - m);
            al[1 - p][s + 2] = m + __logf(w) + e;
        }
        __syncthreads();
        p ^= 1;
    }

    if (s == 0) {
        int L = ys_lens[b];
        int idx = 2 * L;
        float aL = al[p][idx + 2];
        float aP = al[p][idx + 1];
        float m = fmaxf(aL, aP);
        float loss = -(m + __logf(__expf(aL - m) + __expf(aP - m)));
        if (!isfinite(loss) || loss >= 1e29f) loss = 0.f;
        g_loss[b] = loss;
    }
}

// ---------------- kernel 4: final reduce --------------------------------
__global__ void finalize_kernel(float* __restrict__ out) {
    float sum = 0.f;
    for (int i = 0; i < BATCH; i++) sum += g_loss[i];
    out[0] = sum / (float)BATCH;
}

// ---------------- launch --------------------------------------------------
extern "C" void kernel_launch(void* const* d_in, const int* in_sizes, int n_in,
                              void* d_out, int out_size) {
    const float* hs     = (const float*)d_in[0];
    const float* Wm     = (const float*)d_in[1];
    const float* bias   = (const float*)d_in[2];
    const int* hlens    = (const int*)d_in[3];
    const int* ys_pad   = (const int*)d_in[4];
    const int* ys_lens  = (const int*)d_in[5];
    float* out = (float*)d_out;

    cudaFuncSetAttribute(mma_gemm_kernel,
                         cudaFuncAttributeMaxDynamicSharedMemorySize, DYN_SMEM);

    prep_kernel<<<PREP_BLOCKS, 256>>>(hs, Wm, hlens);
    write_slot_kernel<<<BATCH, 128>>>(ys_pad);

    dim3 gemm_grid(NTILES, NROWS / 128);  // (32, 100); suffix tiles early-exit
    mma_gemm_kernel<<<gemm_grid, 256, DYN_SMEM>>>(bias, hlens);

    emit_kernel<<<NROWS, 128>>>(ys_pad, hlens);
    ctc_kernel<<<BATCH, 224>>>(hlens, ys_pad, ys_lens);
    finalize_kernel<<<1, 1>>>(out);
}

// round 12
// speedup vs baseline: 1.7220x; 1.0100x over previous
#include <cuda_runtime.h>
#include <cuda_bf16.h>
#include <math.h>
#include <stdint.h>

#define BATCH 16
#define TLEN 800
#define DDIM 512
#define VOC 4000
#define VPAD 4096
#define LMAX 100
#define SEXT 201
#define NEMIT 101
#define NROWS (BATCH * TLEN)
#define NTILES 32
#define NMTILES 100
#define GSTRIDE 104
#define NEGV (-1e30f)

#define KCHUNK 64
#define NKC 8                 // 512 / 64
#define TILE_BYTES 16384      // 128 rows * 128 B (XOR swizzle)
#define STAGE_BYTES 32768     // A tile + B tile
#define NSTAGE 3
#define DYN_SMEM (NSTAGE * STAGE_BYTES)   // 98304

// prep kernel block ranges
#define PREP_CONV   1600      // NROWS / 8
#define PREP_TRANSW 2048      // (VPAD/32) * (DDIM/32)
#define PREP_INIT   250       // BATCH*VOC / 256
#define PREP_BLOCKS (PREP_CONV + PREP_TRANSW + PREP_INIT)

// ---------------- device scratch ----------------
__device__ __align__(16) __nv_bfloat16 g_Abf[(size_t)NROWS * DDIM];  // compacted
__device__ __align__(16) __nv_bfloat16 g_Wt[(size_t)VPAD * DDIM];
__device__ float g_pmax[NROWS * NTILES];
__device__ float g_psum[NROWS * NTILES];
__device__ float g_gath[(size_t)NROWS * GSTRIDE];
__device__ float g_emit[(size_t)NROWS * NEMIT];   // compacted rows
__device__ int   g_slot[BATCH * VOC];
__device__ int   g_cnt[NMTILES];                  // per-m-tile arrival counters
__device__ float g_loss[BATCH];

// ---------------- inline index helpers ---------------------------------
__device__ __forceinline__ int sum_hlens(const int* __restrict__ hlens) {
    int s = 0;
#pragma unroll
    for (int i = 0; i < BATCH; i++) s += __ldg(&hlens[i]);
    return s;
}
__device__ __forceinline__ int batch_of(int row, const int* __restrict__ hlens) {
    int off = 0, b = 0;
#pragma unroll
    for (int i = 0; i < BATCH; i++) {
        int nx = off + __ldg(&hlens[i]);
        if (row >= nx) { off = nx; b = i + 1; }
    }
    return b;
}
__device__ __forceinline__ int off_of_batch(int b, const int* __restrict__ hlens) {
    int off = 0;
#pragma unroll
    for (int i = 0; i < BATCH; i++)
        if (i < b) off += __ldg(&hlens[i]);
    return off;
}

// ---------------- PTX helpers (compute_103-legal) ----------------------
__device__ __forceinline__ void ldsm4(uint32_t* r, uint32_t addr) {
    asm volatile("ldmatrix.sync.aligned.m8n8.x4.shared.b16 {%0,%1,%2,%3}, [%4];"
                 : "=r"(r[0]), "=r"(r[1]), "=r"(r[2]), "=r"(r[3]) : "r"(addr));
}
__device__ __forceinline__ void mma16816(float* d, const uint32_t* a,
                                         uint32_t b0, uint32_t b1) {
    asm volatile(
        "mma.sync.aligned.m16n8k16.row.col.f32.bf16.bf16.f32 "
        "{%0,%1,%2,%3}, {%4,%5,%6,%7}, {%8,%9}, {%0,%1,%2,%3};"
        : "+f"(d[0]), "+f"(d[1]), "+f"(d[2]), "+f"(d[3])
        : "r"(a[0]), "r"(a[1]), "r"(a[2]), "r"(a[3]), "r"(b0), "r"(b1));
}
#define CP16(dst, src) \
    asm volatile("cp.async.cg.shared.global [%0], [%1], 16;" :: "r"(dst), "l"(src))
#define CPCOMMIT() asm volatile("cp.async.commit_group;")
#define CPWAIT1()  asm volatile("cp.async.wait_group 1;")

// ---------------- kernel 0: fused prep (convA + transW + init) ---------
__global__ __launch_bounds__(256) void prep_kernel(const float* __restrict__ src,
                                                   const float* __restrict__ W,
                                                   const int* __restrict__ hlens) {
    const int bid = blockIdx.x;
    const int tid = threadIdx.x;

    if (bid < PREP_CONV) {
        // ---- convA: fp32 -> bf16, row-compacted ----
        int r = bid * 8 + (tid >> 5);
        int lane = tid & 31;
        int b = r / TLEN, t = r - b * TLEN;
        if (t >= __ldg(&hlens[b])) return;
        int dst = off_of_batch(b, hlens) + t;
        const float* p = src + (size_t)r * DDIM;
        __nv_bfloat16* q = g_Abf + (size_t)dst * DDIM;
#pragma unroll
        for (int i = 0; i < 4; i++) {
            float4 v = *(const float4*)(p + lane * 4 + i * 128);
            *(__nv_bfloat162*)(q + lane * 4 + i * 128)     = __floats2bfloat162_rn(v.x, v.y);
            *(__nv_bfloat162*)(q + lane * 4 + i * 128 + 2) = __floats2bfloat162_rn(v.z, v.w);
        }
    } else if (bid < PREP_CONV + PREP_TRANSW) {
        // ---- transW: W[k][v] -> g_Wt[v][k] bf16 ----
        __shared__ float sm[32][33];
        int idx = bid - PREP_CONV;
        int v0 = (idx & 127) * 32, k0 = (idx >> 7) * 32;
        int tx = tid & 31, ty = tid >> 5;   // 32 x 8
#pragma unroll
        for (int r = 0; r < 4; r++) {
            int k = k0 + ty + r * 8, v = v0 + tx;
            sm[ty + r * 8][tx] = (v < VOC) ? W[(size_t)k * VOC + v] : 0.f;
        }
        __syncthreads();
#pragma unroll
        for (int r = 0; r < 4; r++) {
            int v = v0 + ty + r * 8, k = k0 + tx;
            g_Wt[(size_t)v * DDIM + k] = __float2bfloat16(sm[tx][ty + r * 8]);
        }
    } else {
        // ---- slot map + counter init ----
        int i = (bid - PREP_CONV - PREP_TRANSW) * 256 + tid;
        if (i < BATCH * VOC) g_slot[i] = -1;
        if (i < NMTILES) g_cnt[i] = 0;
    }
}

// ---------------- kernel 0b: write label slots -------------------------
__global__ void write_slot_kernel(const int* __restrict__ ys_pad) {
    int b = blockIdx.x;
    int j = threadIdx.x;
    if (j < LMAX) g_slot[b * VOC + ys_pad[b * LMAX + j]] = j + 1;
    if (j == LMAX) g_slot[b * VOC + 0] = 0;
}

// ---------------- kernel 1: GEMM + fused LSE/emit (last-arriver) -------
__global__ __launch_bounds__(256, 2)
void mma_gemm_kernel(const float* __restrict__ bias,
                     const int* __restrict__ hlens,
                     const int* __restrict__ ys_pad) {
    extern __shared__ __align__(128) char dynbuf[];
    __shared__ float bias_s[128];
    __shared__ int   slot_s[256];
    __shared__ int   info_s[128];
    __shared__ float redM[128 * 5];
    __shared__ float redS[128 * 5];
    __shared__ float lse_sh[128];
    __shared__ int   is_last;

    const int n0 = blockIdx.x * 128, m0 = blockIdx.y * 128;
    const int nlive = sum_hlens(hlens);
    if (m0 >= nlive) return;   // compacted: dead tiles are a suffix

    const int rb0 = batch_of(m0, hlens);
    const int rlast = (m0 + 127 < nlive) ? (m0 + 127) : (nlive - 1);
    const int rb1 = batch_of(rlast, hlens);

    const uint32_t sbD = (uint32_t)__cvta_generic_to_shared(dynbuf);
    const int tid = threadIdx.x;
    const int lane = tid & 31, wid = tid >> 5;
    const int wm = wid >> 2, wn = wid & 3;

    // cp.async mapping: 128 rows x 8 chunks of 16B per operand per stage
    const int crow = tid >> 3;
    const int cc8  = tid & 7;
    const uint32_t cxr = (uint32_t)((crow & 7) << 4);
    const uint32_t cdst = (uint32_t)(crow * 128 + ((cc8 * 16) ^ cxr));
    const __nv_bfloat16* Ab = g_Abf + (size_t)m0 * DDIM;
    const __nv_bfloat16* Bb = g_Wt  + (size_t)n0 * DDIM;

#pragma unroll
    for (int s = 0; s < NSTAGE - 1; s++) {
        uint32_t dst = sbD + s * STAGE_BYTES;
        int k0 = s * KCHUNK;
#pragma unroll
        for (int i = 0; i < 4; i++) {
            CP16(dst + cdst + i * (32 * 128),
                 Ab + (size_t)(crow + 32 * i) * DDIM + k0 + cc8 * 8);
            CP16(dst + TILE_BYTES + cdst + i * (32 * 128),
                 Bb + (size_t)(crow + 32 * i) * DDIM + k0 + cc8 * 8);
        }
        CPCOMMIT();
    }

    if (tid < 128) {
        int gc = n0 + tid;
        bias_s[tid]       = (gc < VOC) ? bias[gc] : 0.f;
        slot_s[tid]       = (gc < VOC) ? g_slot[rb0 * VOC + gc] : -1;
        slot_s[128 + tid] = (gc < VOC) ? g_slot[rb1 * VOC + gc] : -1;
        info_s[tid]       = batch_of(m0 + tid, hlens);
    }

    float acc[4][16];
#pragma unroll
    for (int i = 0; i < 4; i++)
#pragma unroll
        for (int j = 0; j < 16; j++) acc[i][j] = 0.f;

    const int arow = wm * 64 + (lane & 15);
    const int brow = wn * 32 + (lane & 15);
    const uint32_t axr = (uint32_t)((arow & 7) << 4);
    const uint32_t bxr = (uint32_t)((brow & 7) << 4);
    const uint32_t ahi = (uint32_t)((lane >> 4) << 4);

#pragma unroll
    for (int kc = 0; kc < NKC; kc++) {
        CPWAIT1();
        __syncthreads();   // stage kc visible (also publishes bias/slot/info smem)

        int ks = kc + NSTAGE - 1;
        if (ks < NKC) {
            uint32_t dst = sbD + (ks % 3) * STAGE_BYTES;
            int k0 = ks * KCHUNK;
#pragma unroll
            for (int i = 0; i < 4; i++) {
                CP16(dst + cdst + i * (32 * 128),
                     Ab + (size_t)(crow + 32 * i) * DDIM + k0 + cc8 * 8);
                CP16(dst + TILE_BYTES + cdst + i * (32 * 128),
                     Bb + (size_t)(crow + 32 * i) * DDIM + k0 + cc8 * 8);
            }
        }
        CPCOMMIT();

        const uint32_t base = sbD + (kc % 3) * STAGE_BYTES;
#pragma unroll
        for (int h = 0; h < 4; h++) {
            const uint32_t acol = ((uint32_t)(h * 32) | ahi) ^ axr;
            const uint32_t bcol = ((uint32_t)(h * 32) | ahi) ^ bxr;
            uint32_t af[4][4], bf[2][4];
#pragma unroll
            for (int mf = 0; mf < 4; mf++)
                ldsm4(af[mf], base + (uint32_t)((arow + mf * 16) * 128) + acol);
#pragma unroll
            for (int jg = 0; jg < 2; jg++)
                ldsm4(bf[jg], base + TILE_BYTES + (uint32_t)((brow + jg * 16) * 128) + bcol);
#pragma unroll
            for (int mf = 0; mf < 4; mf++) {
#pragma unroll
                for (int jg = 0; jg < 2; jg++) {
                    mma16816(&acc[mf][(jg * 2 + 0) * 4], af[mf], bf[jg][0], bf[jg][2]);
                    mma16816(&acc[mf][(jg * 2 + 1) * 4], af[mf], bf[jg][1], bf[jg][3]);
                }
            }
        }
    }

    // ---- epilogue: bias + online max/sumexp + label gather ----
    float biasv[8]; bool validv[8]; int sl0[8], sl1[8];
#pragma unroll
    for (int nf = 0; nf < 4; nf++)
#pragma unroll
        for (int e = 0; e < 2; e++) {
            int idx = nf * 2 + e;
            int c = wn * 32 + nf * 8 + (lane & 3) * 2 + e;
            biasv[idx]  = bias_s[c];
            validv[idx] = (n0 + c) < VOC;
            sl0[idx] = slot_s[c];
            sl1[idx] = slot_s[128 + c];
        }
#pragma unroll
    for (int mf = 0; mf < 4; mf++)
#pragma unroll
        for (int k = 0; k < 16; k++)
            acc[mf][k] += biasv[(k >> 2) * 2 + (k & 1)];

#pragma unroll
    for (int mf = 0; mf < 4; mf++) {
#pragma unroll
        for (int half = 0; half < 2; half++) {
            int r = wm * 64 + mf * 16 + half * 8 + (lane >> 2);
            int grow = m0 + r;
            bool live = grow < nlive;
            int bb = (info_s[r] != rb0) ? 1 : 0;
            float m = -3.4e38f, s = 0.f;
            if (live) {
#pragma unroll
                for (int ci = 0; ci < 8; ci++) {
                    float v = acc[mf][(ci >> 1) * 4 + half * 2 + (ci & 1)];
                    if (validv[ci]) m = fmaxf(m, v);
                }
#pragma unroll
                for (int ci = 0; ci < 8; ci++) {
                    float v = acc[mf][(ci >> 1) * 4 + half * 2 + (ci & 1)];
                    if (validv[ci]) {
                        s += __expf(v - m);
                        int sl = bb ? sl1[ci] : sl0[ci];
                        if (sl >= 0) g_gath[(size_t)grow * GSTRIDE + sl] = v;
                    }
                }
            }
#pragma unroll
            for (int off = 1; off <= 2; off <<= 1) {
                float om = __shfl_xor_sync(~0u, m, off);
                float os = __shfl_xor_sync(~0u, s, off);
                float nm = fmaxf(m, om);
                s = s * __expf(m - nm) + os * __expf(om - nm);
                m = nm;
            }
            if ((lane & 3) == 0) { redM[r * 5 + wn] = m; redS[r * 5 + wn] = s; }
        }
    }
    __syncthreads();
    if (tid < 128) {
        float M = redM[tid * 5 + 0], S = redS[tid * 5 + 0];
#pragma unroll
        for (int w = 1; w < 4; w++) {
            float m2 = redM[tid * 5 + w], s2 = redS[tid * 5 + w];
            float Mn = fmaxf(M, m2);
            S = S * __expf(M - Mn) + s2 * __expf(m2 - Mn);
            M = Mn;
        }
        g_pmax[(m0 + tid) * NTILES + blockIdx.x] = M;
        g_psum[(m0 + tid) * NTILES + blockIdx.x] = S;
    }

    // ---- last-arriver fused LSE + emit for this m-tile ----
    __threadfence();            // publish this CTA's pmax/psum/gath
    __syncthreads();            // all threads' writes fenced before counting
    if (tid == 0)
        is_last = (atomicAdd(&g_cnt[blockIdx.y], 1) == NTILES - 1);
    __syncthreads();
    if (!is_last) return;
    __threadfence();            // acquire other CTAs' writes

    if (tid < 128) {
        int row = m0 + tid;
        if (row < nlive) {
            float M = -3.4e38f, S = 0.f;
#pragma unroll 4
            for (int w = 0; w < NTILES; w++) {
                float pm = g_pmax[row * NTILES + w];
                float ps = g_psum[row * NTILES + w];
                float Mn = fmaxf(M, pm);
                S = S * __expf(M - Mn) + ps * __expf(pm - Mn);
                M = Mn;
            }
            lse_sh[tid] = M + __logf(S);
        }
    }
    __syncthreads();
    for (int idx = tid; idx < 128 * NEMIT; idx += 256) {
        int r = idx / NEMIT, j = idx - r * NEMIT;
        int row = m0 + r;
        if (row < nlive) {
            int b = info_s[r];
            int col = (j == 0) ? 0 : ys_pad[b * LMAX + j - 1];
            int slot = g_slot[b * VOC + col];
            g_emit[(size_t)row * NEMIT + j] =
                g_gath[(size_t)row * GSTRIDE + slot] - lse_sh[r];
        }
    }
}

// ---------------- kernel 2: CTC forward recursion (double-step) --------
__global__ __launch_bounds__(224) void ctc_kernel(const int* __restrict__ hlens,
                                                  const int* __restrict__ ys_pad,
                                                  const int* __restrict__ ys_lens) {
    const int b = blockIdx.x;
    const int s = threadIdx.x;
    __shared__ float al[2][SEXT + 4];   // alpha[x] at al[x+4]; al[0..3] guards

    const int roff = off_of_batch(b, hlens);
    const float* eb = g_emit + (size_t)roff * NEMIT;
    const bool act = s < SEXT;

    const int j0 = (s & 1) ? ((s >> 1) + 1) : 0;
    const int j1 = ((s - 1) & 1) ? (((s - 1) >> 1) + 1) : 0;   // col of s-1
    const int j2 = ((s - 2) & 1) ? (((s - 2) >> 1) + 1) : 0;   // col of s-2

    // skip flags for s, s-1, s-2
    bool sk0 = false, sk1 = false, sk2 = false;
    if (act) {
        if ((s & 1) && s >= 3)
            sk0 = ys_pad[b * LMAX + (s >> 1)] != ys_pad[b * LMAX + (s >> 1) - 1];
        if (((s - 1) & 1) && (s - 1) >= 3)
            sk1 = ys_pad[b * LMAX + ((s - 1) >> 1)] != ys_pad[b * LMAX + ((s - 1) >> 1) - 1];
        if (((s - 2) & 1) && (s - 2) >= 3)
            sk2 = ys_pad[b * LMAX + ((s - 2) >> 1)] != ys_pad[b * LMAX + ((s - 2) >> 1) - 1];
    }

    if (s < 4) { al[0][s] = NEGV; al[1][s] = NEGV; }
    if (act) al[0][s + 4] = (s < 2) ? eb[j0] : NEGV;

    const int hl = hlens[b];
    __syncthreads();

    int p = 0;
    const int nsteps = hl - 1;
    const int ndouble = nsteps >> 1;
    for (int d = 0; d < ndouble; d++) {
        const int t = 1 + 2 * d;
        if (act) {
            float e0a = eb[(size_t)t * NEMIT + j0];
            float e1a = (s >= 1) ? eb[(size_t)t * NEMIT + j1] : 0.f;
            float e2a = (s >= 2) ? eb[(size_t)t * NEMIT + j2] : 0.f;
            float e0b = eb[(size_t)(t + 1) * NEMIT + j0];

            float a0 = al[p][s + 4];   // a[s]
            float a1 = al[p][s + 3];   // a[s-1]
            float a2 = al[p][s + 2];   // a[s-2]
            float a3 = al[p][s + 1];   // a[s-3]
            float a4 = al[p][s];       // a[s-4]

            float b0, b1, b2;
            {
                float x2 = sk0 ? a2 : NEGV;
                float m = fmaxf(a0, fmaxf(a1, x2));
                b0 = m + __logf(__expf(a0 - m) + __expf(a1 - m) + __expf(x2 - m)) + e0a;
            }
            if (s >= 1) {
                float x2 = sk1 ? a3 : NEGV;
                float m = fmaxf(a1, fmaxf(a2, x2));
                b1 = m + __logf(__expf(a1 - m) + __expf(a2 - m) + __expf(x2 - m)) + e1a;
            } else b1 = NEGV;
            if (s >= 2) {
                float x2 = sk2 ? a4 : NEGV;
                float m = fmaxf(a2, fmaxf(a3, x2));
                b2 = m + __logf(__expf(a2 - m) + __expf(a3 - m) + __expf(x2 - m)) + e2a;
            } else b2 = NEGV;
            {
                float x2 = sk0 ? b2 : NEGV;
                float m = fmaxf(b0, fmaxf(b1, x2));
                al[1 - p][s + 4] =
                    m + __logf(__expf(b0 - m) + __expf(b1 - m) + __expf(x2 - m)) + e0b;
            }
        }
        __syncthreads();
        p ^= 1;
    }
    if (nsteps & 1) {
        const int t = nsteps;   // = hl-1
        if (act) {
            float e = eb[(size_t)t * NEMIT + j0];
            float a0 = al[p][s + 4], a1 = al[p][s + 3];
            float x2 = sk0 ? al[p][s + 2] : NEGV;
            float m = fmaxf(a0, fmaxf(a1, x2));
            al[1 - p][s + 4] =
                m + __logf(__expf(a0 - m) + __expf(a1 - m) + __expf(x2 - m)) + e;
        }
        __syncthreads();
        p ^= 1;
    }

    if (s == 0) {
        int L = ys_lens[b];
        int idx = 2 * L;
        float aL = al[p][idx + 4];
        float aP = al[p][idx + 3];
        float m = fmaxf(aL, aP);
        float loss = -(m + __logf(__expf(aL - m) + __expf(aP - m)));
        if (!isfinite(loss) || loss >= 1e29f) loss = 0.f;
        g_loss[b] = loss;
    }
}

// ---------------- kernel 3: final reduce --------------------------------
__global__ void finalize_kernel(float* __restrict__ out) {
    float sum = 0.f;
    for (int i = 0; i < BATCH; i++) sum += g_loss[i];
    out[0] = sum / (float)BATCH;
}

// ---------------- launch --------------------------------------------------
extern "C" void kernel_launch(void* const* d_in, const int* in_sizes, int n_in,
                              void* d_out, int out_size) {
    const float* hs     = (const float*)d_in[0];
    const float* Wm     = (const float*)d_in[1];
    const float* bias   = (const float*)d_in[2];
    const int* hlens    = (const int*)d_in[3];
    const int* ys_pad   = (const int*)d_in[4];
    const int* ys_lens  = (const int*)d_in[5];
    float* out = (float*)d_out;

    cudaFuncSetAttribute(mma_gemm_kernel,
                         cudaFuncAttributeMaxDynamicSharedMemorySize, DYN_SMEM);

    prep_kernel<<<PREP_BLOCKS, 256>>>(hs, Wm, hlens);
    write_slot_kernel<<<BATCH, 128>>>(ys_pad);

    dim3 gemm_grid(NTILES, NROWS / 128);  // (32, 100); suffix tiles early-exit
    mma_gemm_kernel<<<gemm_grid, 256, DYN_SMEM>>>(bias, hlens, ys_pad);

    ctc_kernel<<<BATCH, 224>>>(hlens, ys_pad, ys_lens);
    finalize_kernel<<<1, 1>>>(out);
}